// round 2
// baseline (speedup 1.0000x reference)
#include <cuda_runtime.h>
#include <math.h>

// Problem constants
#define NB   16          // batch
#define NC   256         // channels
#define NHW  1024        // H*W
#define NG   32          // groups
#define CHW  (NC*NHW)    // 262144 per-batch activation size

// ---------------- scratch (device globals; no runtime allocation) ----------
__device__ float g_t0[NB*CHW];
__device__ float g_t1[NB*CHW];
__device__ float g_t2[NB*CHW];
__device__ float g_h [NB*CHW];
__device__ float g_qkv[NB*3*CHW];         // 50 MB
__device__ float g_att[(long)NB*NHW*NHW]; // 67 MB
__device__ float g_film[NB*NC];
__device__ float g_mean[NB*NG];
__device__ float g_rstd[NB*NG];

// ---------------- FiLM: film[b][co] = emb[b] @ noise_w + noise_b -----------
__global__ void film_kernel(const float* __restrict__ emb,
                            const float* __restrict__ w,
                            const float* __restrict__ nb,
                            float* __restrict__ film) {
    int b = blockIdx.x;
    int co = threadIdx.x;
    __shared__ float e[NC];
    e[co] = emb[b*NC + co];
    __syncthreads();
    float acc = nb[co];
    #pragma unroll 8
    for (int k = 0; k < NC; k++) acc += e[k] * w[k*NC + co];
    film[b*NC + co] = acc;
}

// ---------------- GroupNorm stats: per (b,g) over 8*1024 contiguous floats -
__global__ void gn_stats_kernel(const float* __restrict__ x,
                                float* __restrict__ mean,
                                float* __restrict__ rstd) {
    int bg = blockIdx.x;                      // 0..511
    const float* p = x + (long)bg * 8192;
    int t = threadIdx.x;
    float s = 0.f, s2 = 0.f;
    for (int i = t; i < 8192; i += 256) {
        float v = p[i];
        s += v; s2 += v*v;
    }
    __shared__ float sh[256], sh2[256];
    sh[t] = s; sh2[t] = s2;
    __syncthreads();
    for (int o = 128; o > 0; o >>= 1) {
        if (t < o) { sh[t] += sh[t+o]; sh2[t] += sh2[t+o]; }
        __syncthreads();
    }
    if (t == 0) {
        float m = sh[0] * (1.f/8192.f);
        float var = sh2[0] * (1.f/8192.f) - m*m;
        mean[bg] = m;
        rstd[bg] = rsqrtf(var + 1e-5f);
    }
}

// ---------------- GroupNorm apply (+optional SiLU) --------------------------
__global__ void gn_apply_kernel(const float* __restrict__ x,
                                const float* __restrict__ mean,
                                const float* __restrict__ rstd,
                                const float* __restrict__ scale,
                                const float* __restrict__ bias,
                                float* __restrict__ y,
                                int do_silu) {
    long idx = (long)blockIdx.x * 256 + threadIdx.x;   // grid covers NB*CHW
    int b   = (int)(idx >> 18);                        // /262144
    int ofs = (int)(idx & (CHW-1));
    int g   = ofs >> 13;                               // /8192
    int c   = ofs >> 10;                               // /1024 -> channel
    int bg  = b*NG + g;
    float v = (x[idx] - mean[bg]) * rstd[bg] * scale[c] + bias[c];
    if (do_silu) v = v / (1.f + expf(-v));
    y[idx] = v;
}

// ---------------- Softmax over rows of 1024 ---------------------------------
__global__ void softmax_kernel(float* __restrict__ S) {
    long row = blockIdx.x;                    // NB*NHW rows
    float* p = S + row * NHW;
    int t = threadIdx.x;
    float v[4];
    float mx = -1e30f;
    #pragma unroll
    for (int j = 0; j < 4; j++) { v[j] = p[t + j*256]; mx = fmaxf(mx, v[j]); }
    __shared__ float sh[256];
    sh[t] = mx; __syncthreads();
    for (int o = 128; o > 0; o >>= 1) { if (t < o) sh[t] = fmaxf(sh[t], sh[t+o]); __syncthreads(); }
    mx = sh[0]; __syncthreads();
    float s = 0.f;
    #pragma unroll
    for (int j = 0; j < 4; j++) { v[j] = expf(v[j] - mx); s += v[j]; }
    sh[t] = s; __syncthreads();
    for (int o = 128; o > 0; o >>= 1) { if (t < o) sh[t] += sh[t+o]; __syncthreads(); }
    float inv = 1.f / sh[0];
    #pragma unroll
    for (int j = 0; j < 4; j++) p[t + j*256] = v[j] * inv;
}

// ---------------- Generic batched 128x64x16 SGEMM ---------------------------
// C[b][m][n] = alpha * sum_k A(m,k)*B(k,n)  (+bias[m]) (+film[b][m])
//             (+addsrc[b][m][n]) (+= C if accumulate)
// TA=0: A row-major [M][K];  TA=1: A is [K][M] (lda = M)
// TB=0: B is [K][N];         TB=1: B is [N][K] (ldb = K)
// IMC : B is an image [Ci][32][32], K = Ci*9, im2col on the fly (pad=1)
// 256 threads, 8x4 register microtile.
template<int TA, int TB, bool IMC>
__global__ __launch_bounds__(256)
void gemm128_kernel(const float* __restrict__ A,
                    const float* __restrict__ Bp,
                    float* __restrict__ Cp,
                    int M, int N, int K,
                    long sA, long sB, long sC,
                    float alpha,
                    const float* __restrict__ bias,
                    const float* __restrict__ film,
                    const float* __restrict__ addsrc,
                    int accumulate) {
    __shared__ float As[16*128];   // As[k][m]
    __shared__ float Bs[16*64];    // Bs[k][n]
    int b  = blockIdx.z;
    const float* Ab = A  + (long)b * sA;
    const float* Bb = Bp + (long)b * sB;
    float*       Cb = Cp + (long)b * sC;
    int m0 = blockIdx.y * 128;
    int n0 = blockIdx.x * 64;
    int t  = threadIdx.x;                // 256 threads
    int tmg = (t >> 4) << 3;             // 0..120, 8 rows per thread
    int tn  = (t & 15) << 2;             // 0..60, 4 cols per thread
    float acc[8][4] = {};

    for (int kk = 0; kk < K; kk += 16) {
        // ---- load A tile (128 x 16) into As[k][m] ----
        if (TA == 0) {
            // 512 float4s: f -> m = f>>2, kq = (f&3)*4
            #pragma unroll
            for (int r = 0; r < 2; r++) {
                int f  = t + r*256;
                int m  = f >> 2;
                int kq = (f & 3) << 2;
                float4 v = *reinterpret_cast<const float4*>(Ab + (long)(m0+m)*K + kk + kq);
                As[(kq+0)*128 + m] = v.x;
                As[(kq+1)*128 + m] = v.y;
                As[(kq+2)*128 + m] = v.z;
                As[(kq+3)*128 + m] = v.w;
            }
        } else {
            // A is [K][M]: f -> k = f>>5, mq = (f&31)*4 ; direct copy
            #pragma unroll
            for (int r = 0; r < 2; r++) {
                int f  = t + r*256;
                int k  = f >> 5;
                int mq = (f & 31) << 2;
                *reinterpret_cast<float4*>(&As[k*128 + mq]) =
                    *reinterpret_cast<const float4*>(Ab + (long)(kk+k)*M + m0 + mq);
            }
        }
        // ---- load B tile (16 x 64) into Bs[k][n] ----
        if (IMC) {
            int n  = t & 63;
            int kr = t >> 6;
            int ng = n0 + n;
            int h = ng >> 5, w = ng & 31;
            #pragma unroll
            for (int j = 0; j < 4; j++) {
                int kl = kr + j*4;
                int kg = kk + kl;
                int ci = kg / 9;
                int r  = kg - ci*9;
                int kh = r / 3;
                int kw = r - kh*3;
                int ih = h + kh - 1, iw = w + kw - 1;
                float v = 0.f;
                if (ih >= 0 && ih < 32 && iw >= 0 && iw < 32)
                    v = Bb[ci*NHW + ih*32 + iw];
                Bs[kl*64 + n] = v;
            }
        } else if (TB == 0) {
            int k  = t >> 4;
            int nq = (t & 15) << 2;
            *reinterpret_cast<float4*>(&Bs[k*64 + nq]) =
                *reinterpret_cast<const float4*>(Bb + (long)(kk+k)*N + n0 + nq);
        } else {
            int n  = t >> 2;
            int kq = (t & 3) << 2;
            float4 f = *reinterpret_cast<const float4*>(Bb + (long)(n0+n)*K + kk + kq);
            Bs[(kq+0)*64 + n] = f.x;
            Bs[(kq+1)*64 + n] = f.y;
            Bs[(kq+2)*64 + n] = f.z;
            Bs[(kq+3)*64 + n] = f.w;
        }
        __syncthreads();
        // ---- compute: 8x4 microtile ----
        #pragma unroll
        for (int k = 0; k < 16; k++) {
            float4 a0 = *reinterpret_cast<float4*>(&As[k*128 + tmg]);
            float4 a1 = *reinterpret_cast<float4*>(&As[k*128 + tmg + 4]);
            float4 bv = *reinterpret_cast<float4*>(&Bs[k*64 + tn]);
            float av[8] = {a0.x, a0.y, a0.z, a0.w, a1.x, a1.y, a1.z, a1.w};
            float bb[4] = {bv.x, bv.y, bv.z, bv.w};
            #pragma unroll
            for (int i = 0; i < 8; i++)
                #pragma unroll
                for (int j = 0; j < 4; j++)
                    acc[i][j] += av[i] * bb[j];
        }
        __syncthreads();
    }

    // ---- epilogue ----
    #pragma unroll
    for (int i = 0; i < 8; i++) {
        int m = m0 + tmg + i;
        float badd = 0.f;
        if (bias) badd += bias[m];
        if (film) badd += film[b*M + m];
        #pragma unroll
        for (int j = 0; j < 4; j++) {
            int n = n0 + tn + j;
            long idx = (long)m * N + n;
            float v = acc[i][j] * alpha + badd;
            if (addsrc)     v += addsrc[(long)b*sC + idx];
            if (accumulate) v += Cb[idx];
            Cb[idx] = v;
        }
    }
}

// ---------------- host launch ------------------------------------------------
extern "C" void kernel_launch(void* const* d_in, const int* in_sizes, int n_in,
                              void* d_out, int out_size) {
    const float* x          = (const float*)d_in[0];
    const float* noise_emb  = (const float*)d_in[1];
    const float* gn1_scale  = (const float*)d_in[2];
    const float* gn1_bias   = (const float*)d_in[3];
    const float* conv1_w    = (const float*)d_in[4];
    const float* conv1_b    = (const float*)d_in[5];
    const float* noise_w    = (const float*)d_in[6];
    const float* noise_b    = (const float*)d_in[7];
    const float* gn2_scale  = (const float*)d_in[8];
    const float* gn2_bias   = (const float*)d_in[9];
    const float* conv2_w    = (const float*)d_in[10];
    const float* conv2_b    = (const float*)d_in[11];
    const float* res_w      = (const float*)d_in[12];
    const float* res_b      = (const float*)d_in[13];
    const float* agn_scale  = (const float*)d_in[14];
    const float* agn_bias   = (const float*)d_in[15];
    const float* qkv_w      = (const float*)d_in[16];
    const float* out_w      = (const float*)d_in[17];
    const float* out_b      = (const float*)d_in[18];
    float* out = (float*)d_out;

    float *t0, *t1, *t2, *h, *qkv, *att, *film, *mean, *rstd;
    cudaGetSymbolAddress((void**)&t0,   g_t0);
    cudaGetSymbolAddress((void**)&t1,   g_t1);
    cudaGetSymbolAddress((void**)&t2,   g_t2);
    cudaGetSymbolAddress((void**)&h,    g_h);
    cudaGetSymbolAddress((void**)&qkv,  g_qkv);
    cudaGetSymbolAddress((void**)&att,  g_att);
    cudaGetSymbolAddress((void**)&film, g_film);
    cudaGetSymbolAddress((void**)&mean, g_mean);
    cudaGetSymbolAddress((void**)&rstd, g_rstd);

    const int ELTS = NB * CHW;            // 4194304
    const int EW_GRID = ELTS / 256;       // 16384

    // FiLM vector
    film_kernel<<<NB, NC>>>(noise_emb, noise_w, noise_b, film);

    // GN1 + SiLU
    gn_stats_kernel<<<NB*NG, 256>>>(x, mean, rstd);
    gn_apply_kernel<<<EW_GRID, 256>>>(x, mean, rstd, gn1_scale, gn1_bias, t0, 1);

    // conv1 (3x3, im2col GEMM) + FiLM add fused in epilogue
    gemm128_kernel<0,0,true><<<dim3(16,2,NB), 256>>>(
        conv1_w, t0, t1, NC, NHW, NC*9, 0, CHW, CHW, 1.f,
        conv1_b, film, nullptr, 0);

    // GN2 + SiLU
    gn_stats_kernel<<<NB*NG, 256>>>(t1, mean, rstd);
    gn_apply_kernel<<<EW_GRID, 256>>>(t1, mean, rstd, gn2_scale, gn2_bias, t2, 1);

    // residual 1x1 conv -> h
    gemm128_kernel<0,0,false><<<dim3(16,2,NB), 256>>>(
        res_w, x, h, NC, NHW, NC, 0, CHW, CHW, 1.f,
        res_b, nullptr, nullptr, 0);

    // conv2 (3x3) accumulates into h
    gemm128_kernel<0,0,true><<<dim3(16,2,NB), 256>>>(
        conv2_w, t2, h, NC, NHW, NC*9, 0, CHW, CHW, 1.f,
        conv2_b, nullptr, nullptr, 1);

    // attention GroupNorm (no SiLU) -> t0
    gn_stats_kernel<<<NB*NG, 256>>>(h, mean, rstd);
    gn_apply_kernel<<<EW_GRID, 256>>>(h, mean, rstd, agn_scale, agn_bias, t0, 0);

    // qkv 1x1 conv (no bias): [768x256] @ [256x1024]
    gemm128_kernel<0,0,false><<<dim3(16,6,NB), 256>>>(
        qkv_w, t0, qkv, 3*NC, NHW, NC, 0, CHW, (long)3*CHW, 1.f,
        nullptr, nullptr, nullptr, 0);

    // scores: S[b][s][t] = (1/16) * sum_d q[d][s] k[d][t]   (A is [K][M])
    gemm128_kernel<1,0,false><<<dim3(16,8,NB), 256>>>(
        qkv /*q*/, qkv + CHW /*k*/, att, NHW, NHW, NC,
        (long)3*CHW, (long)3*CHW, (long)NHW*NHW, 0.0625f,
        nullptr, nullptr, nullptr, 0);

    // softmax rows
    softmax_kernel<<<NB*NHW, 256>>>(att);

    // AV: O[b][d][s] = sum_t v[d][t] S[s][t]   (B transposed) -> t2
    gemm128_kernel<0,1,false><<<dim3(16,2,NB), 256>>>(
        qkv + 2*CHW /*v*/, att, t2, NC, NHW, NHW,
        (long)3*CHW, (long)NHW*NHW, CHW, 1.f,
        nullptr, nullptr, nullptr, 0);

    // out 1x1 conv + bias + residual h -> d_out
    gemm128_kernel<0,0,false><<<dim3(16,2,NB), 256>>>(
        out_w, t2, out, NC, NHW, NC, 0, CHW, CHW, 1.f,
        out_b, nullptr, h, 0);
}

// round 5
// speedup vs baseline: 2.4707x; 2.4707x over previous
#include <cuda_runtime.h>
#include <math.h>
#include <stdint.h>

// Problem constants
#define NB   16          // batch
#define NC   256         // channels
#define NHW  1024        // H*W
#define NG   32          // groups
#define CHW  (NC*NHW)    // 262144 per-batch activation size

// ---------------- scratch (device globals; no runtime allocation) ----------
__device__ float g_t0[NB*CHW];
__device__ float g_t1[NB*CHW];
__device__ float g_t2[NB*CHW];
__device__ float g_h [NB*CHW];
__device__ float g_qkv[NB*3*CHW];         // 50 MB
__device__ float g_att[(long)NB*NHW*NHW]; // 67 MB
__device__ float g_film[NB*NC];
__device__ float g_mean[NB*NG];
__device__ float g_rstd[NB*NG];

// ---------------- FiLM: film[b][co] = emb[b] @ noise_w + noise_b -----------
__global__ void film_kernel(const float* __restrict__ emb,
                            const float* __restrict__ w,
                            const float* __restrict__ nb,
                            float* __restrict__ film) {
    int b = blockIdx.x;
    int co = threadIdx.x;
    __shared__ float e[NC];
    e[co] = emb[b*NC + co];
    __syncthreads();
    float acc = nb[co];
    #pragma unroll 8
    for (int k = 0; k < NC; k++) acc += e[k] * w[k*NC + co];
    film[b*NC + co] = acc;
}

// ---------------- GroupNorm stats ------------------------------------------
__global__ void gn_stats_kernel(const float* __restrict__ x,
                                float* __restrict__ mean,
                                float* __restrict__ rstd) {
    int bg = blockIdx.x;                      // 0..511
    const float* p = x + (long)bg * 8192;
    int t = threadIdx.x;
    float s = 0.f, s2 = 0.f;
    for (int i = t; i < 8192; i += 256) {
        float v = p[i];
        s += v; s2 += v*v;
    }
    __shared__ float sh[256], sh2[256];
    sh[t] = s; sh2[t] = s2;
    __syncthreads();
    for (int o = 128; o > 0; o >>= 1) {
        if (t < o) { sh[t] += sh[t+o]; sh2[t] += sh2[t+o]; }
        __syncthreads();
    }
    if (t == 0) {
        float m = sh[0] * (1.f/8192.f);
        float var = sh2[0] * (1.f/8192.f) - m*m;
        mean[bg] = m;
        rstd[bg] = rsqrtf(var + 1e-5f);
    }
}

// ---------------- GroupNorm apply (+optional SiLU) --------------------------
__global__ void gn_apply_kernel(const float* __restrict__ x,
                                const float* __restrict__ mean,
                                const float* __restrict__ rstd,
                                const float* __restrict__ scale,
                                const float* __restrict__ bias,
                                float* __restrict__ y,
                                int do_silu) {
    long idx = (long)blockIdx.x * 256 + threadIdx.x;
    int b   = (int)(idx >> 18);
    int ofs = (int)(idx & (CHW-1));
    int g   = ofs >> 13;
    int c   = ofs >> 10;
    int bg  = b*NG + g;
    float v = (x[idx] - mean[bg]) * rstd[bg] * scale[c] + bias[c];
    if (do_silu) v = v / (1.f + expf(-v));
    y[idx] = v;
}

// ---------------- Softmax over rows of 1024 ---------------------------------
__global__ void softmax_kernel(float* __restrict__ S) {
    long row = blockIdx.x;
    float* p = S + row * NHW;
    int t = threadIdx.x;
    float v[4];
    float mx = -1e30f;
    #pragma unroll
    for (int j = 0; j < 4; j++) { v[j] = p[t + j*256]; mx = fmaxf(mx, v[j]); }
    __shared__ float sh[256];
    sh[t] = mx; __syncthreads();
    for (int o = 128; o > 0; o >>= 1) { if (t < o) sh[t] = fmaxf(sh[t], sh[t+o]); __syncthreads(); }
    mx = sh[0]; __syncthreads();
    float s = 0.f;
    #pragma unroll
    for (int j = 0; j < 4; j++) { v[j] = expf(v[j] - mx); s += v[j]; }
    sh[t] = s; __syncthreads();
    for (int o = 128; o > 0; o >>= 1) { if (t < o) sh[t] += sh[t+o]; __syncthreads(); }
    float inv = 1.f / sh[0];
    #pragma unroll
    for (int j = 0; j < 4; j++) p[t + j*256] = v[j] * inv;
}

// ---------------- TF32 helpers ----------------------------------------------
// cvt to .tf32 requires a b32 destination register (ptxas rejects f32 dst).
__device__ __forceinline__ uint32_t to_tf32(float x) {
    uint32_t y;
    asm("cvt.rna.tf32.f32 %0, %1;" : "=r"(y) : "f"(x));
    return y;
}
__device__ __forceinline__ float to_tf32f(float x) {
    return __uint_as_float(to_tf32(x));
}

__device__ __forceinline__ void mma_tf32(float c[4], uint32_t a0, uint32_t a1,
                                         uint32_t a2, uint32_t a3,
                                         uint32_t b0, uint32_t b1) {
    asm volatile(
        "mma.sync.aligned.m16n8k8.row.col.f32.tf32.tf32.f32 "
        "{%0,%1,%2,%3}, {%4,%5,%6,%7}, {%8,%9}, {%0,%1,%2,%3};\n"
        : "+f"(c[0]), "+f"(c[1]), "+f"(c[2]), "+f"(c[3])
        : "r"(a0), "r"(a1), "r"(a2), "r"(a3), "r"(b0), "r"(b1));
}

// ---------------- Batched 128x128x16 TF32 tensor-core GEMM ------------------
// Double-buffered shared staging: fetch(kk+16)->regs, compute(stage), store,
// one __syncthreads per k-tile.
// C[b][m][n] = alpha * sum_k A(m,k)*B(k,n) (+bias[m]) (+film[b][m])
//             (+addsrc[b][m][n]) (+= C if accumulate)
// TA=0: A row-major [M][K];  TA=1: A is [K][M] (lda = M)
// TB=0: B is [K][N];         TB=1: B is [N][K] (ldb = K)
// IMC : B is an image [Ci][32][32], K = Ci*9, im2col on the fly (pad=1)
#define SAS 136   // shared strides; 136 mod 32 == 8 -> conflict-free frag loads
#define SBS 136

template<int TA, int TB, bool IMC>
__global__ __launch_bounds__(256)
void gemm_tc_kernel(const float* __restrict__ A,
                    const float* __restrict__ Bp,
                    float* __restrict__ Cp,
                    int M, int N, int K,
                    long sA, long sB, long sC,
                    float alpha,
                    const float* __restrict__ bias,
                    const float* __restrict__ film,
                    const float* __restrict__ addsrc,
                    int accumulate) {
    __shared__ float As[2][16*SAS];   // As[st][k][m], tf32-converted bits
    __shared__ float Bs[2][16*SBS];   // Bs[st][k][n], tf32-converted bits

    int b  = blockIdx.z;
    const float* Ab = A  + (long)b * sA;
    const float* Bb = Bp + (long)b * sB;
    float*       Cb = Cp + (long)b * sC;
    int m0 = blockIdx.y * 128;
    int n0 = blockIdx.x * 128;
    int t    = threadIdx.x;
    int lane = t & 31;
    int wid  = t >> 5;
    int wm   = wid & 1;          // warp m index (0..1) -> 64 rows
    int wn   = wid >> 1;         // warp n index (0..3) -> 32 cols
    int grp  = lane >> 2;        // 0..7
    int qd   = lane & 3;         // 0..3

    float acc[4][4][4];
    #pragma unroll
    for (int i = 0; i < 4; i++)
        #pragma unroll
        for (int j = 0; j < 4; j++)
            #pragma unroll
            for (int r = 0; r < 4; r++) acc[i][j][r] = 0.f;

    float aReg[8];
    float bReg[8];

    // ---- fetch helpers (global -> regs) ----
    auto fetchA = [&](int kk) {
        if (TA == 0) {
            #pragma unroll
            for (int r = 0; r < 2; r++) {
                int f = t + r*256;
                int m = f >> 2;
                int kq = (f & 3) << 2;
                float4 v = *reinterpret_cast<const float4*>(Ab + (long)(m0+m)*K + kk + kq);
                aReg[r*4+0] = v.x; aReg[r*4+1] = v.y;
                aReg[r*4+2] = v.z; aReg[r*4+3] = v.w;
            }
        } else {
            #pragma unroll
            for (int r = 0; r < 2; r++) {
                int f = t + r*256;
                int k = f >> 5;
                int mq = (f & 31) << 2;
                float4 v = *reinterpret_cast<const float4*>(Ab + (long)(kk+k)*M + m0 + mq);
                aReg[r*4+0] = v.x; aReg[r*4+1] = v.y;
                aReg[r*4+2] = v.z; aReg[r*4+3] = v.w;
            }
        }
    };
    auto storeA = [&](float* dst) {
        if (TA == 0) {
            #pragma unroll
            for (int r = 0; r < 2; r++) {
                int f = t + r*256;
                int m = f >> 2;
                int kq = (f & 3) << 2;
                dst[(kq+0)*SAS + m] = to_tf32f(aReg[r*4+0]);
                dst[(kq+1)*SAS + m] = to_tf32f(aReg[r*4+1]);
                dst[(kq+2)*SAS + m] = to_tf32f(aReg[r*4+2]);
                dst[(kq+3)*SAS + m] = to_tf32f(aReg[r*4+3]);
            }
        } else {
            #pragma unroll
            for (int r = 0; r < 2; r++) {
                int f = t + r*256;
                int k = f >> 5;
                int mq = (f & 31) << 2;
                float4 w;
                w.x = to_tf32f(aReg[r*4+0]); w.y = to_tf32f(aReg[r*4+1]);
                w.z = to_tf32f(aReg[r*4+2]); w.w = to_tf32f(aReg[r*4+3]);
                *reinterpret_cast<float4*>(&dst[k*SAS + mq]) = w;
            }
        }
    };
    auto fetchB = [&](int kk) {
        if (IMC) {
            int n  = t & 127;
            int kr = t >> 7;
            int ng = n0 + n;
            int hh = ng >> 5, ww = ng & 31;
            #pragma unroll
            for (int j = 0; j < 8; j++) {
                int kl = kr*8 + j;
                int kg = kk + kl;
                int ci = kg / 9;
                int rr = kg - ci*9;
                int kh = rr / 3;
                int kw = rr - kh*3;
                int ih = hh + kh - 1, iw = ww + kw - 1;
                float v = 0.f;
                if (ih >= 0 && ih < 32 && iw >= 0 && iw < 32)
                    v = Bb[ci*NHW + ih*32 + iw];
                bReg[j] = v;
            }
        } else if (TB == 0) {
            #pragma unroll
            for (int r = 0; r < 2; r++) {
                int f = t + r*256;
                int k = f >> 5;
                int nq = (f & 31) << 2;
                float4 v = *reinterpret_cast<const float4*>(Bb + (long)(kk+k)*N + n0 + nq);
                bReg[r*4+0] = v.x; bReg[r*4+1] = v.y;
                bReg[r*4+2] = v.z; bReg[r*4+3] = v.w;
            }
        } else {
            #pragma unroll
            for (int r = 0; r < 2; r++) {
                int f = t + r*256;
                int n = f >> 2;
                int kq = (f & 3) << 2;
                float4 v = *reinterpret_cast<const float4*>(Bb + (long)(n0+n)*K + kk + kq);
                bReg[r*4+0] = v.x; bReg[r*4+1] = v.y;
                bReg[r*4+2] = v.z; bReg[r*4+3] = v.w;
            }
        }
    };
    auto storeB = [&](float* dst) {
        if (IMC) {
            int n  = t & 127;
            int kr = t >> 7;
            #pragma unroll
            for (int j = 0; j < 8; j++) {
                int kl = kr*8 + j;
                dst[kl*SBS + n] = to_tf32f(bReg[j]);
            }
        } else if (TB == 0) {
            #pragma unroll
            for (int r = 0; r < 2; r++) {
                int f = t + r*256;
                int k = f >> 5;
                int nq = (f & 31) << 2;
                float4 w;
                w.x = to_tf32f(bReg[r*4+0]); w.y = to_tf32f(bReg[r*4+1]);
                w.z = to_tf32f(bReg[r*4+2]); w.w = to_tf32f(bReg[r*4+3]);
                *reinterpret_cast<float4*>(&dst[k*SBS + nq]) = w;
            }
        } else {
            #pragma unroll
            for (int r = 0; r < 2; r++) {
                int f = t + r*256;
                int n = f >> 2;
                int kq = (f & 3) << 2;
                dst[(kq+0)*SBS + n] = to_tf32f(bReg[r*4+0]);
                dst[(kq+1)*SBS + n] = to_tf32f(bReg[r*4+1]);
                dst[(kq+2)*SBS + n] = to_tf32f(bReg[r*4+2]);
                dst[(kq+3)*SBS + n] = to_tf32f(bReg[r*4+3]);
            }
        }
    };
    auto compute = [&](int st) {
        const uint32_t* AsU = reinterpret_cast<const uint32_t*>(As[st]);
        const uint32_t* BsU = reinterpret_cast<const uint32_t*>(Bs[st]);
        #pragma unroll
        for (int ks = 0; ks < 16; ks += 8) {
            uint32_t af[4][4];
            #pragma unroll
            for (int mt = 0; mt < 4; mt++) {
                int mb = wm*64 + mt*16 + grp;
                af[mt][0] = AsU[(ks+qd)*SAS + mb];
                af[mt][1] = AsU[(ks+qd)*SAS + mb + 8];
                af[mt][2] = AsU[(ks+4+qd)*SAS + mb];
                af[mt][3] = AsU[(ks+4+qd)*SAS + mb + 8];
            }
            uint32_t bf[4][2];
            #pragma unroll
            for (int nt = 0; nt < 4; nt++) {
                int nb = wn*32 + nt*8 + grp;
                bf[nt][0] = BsU[(ks+qd)*SBS + nb];
                bf[nt][1] = BsU[(ks+4+qd)*SBS + nb];
            }
            #pragma unroll
            for (int mt = 0; mt < 4; mt++)
                #pragma unroll
                for (int nt = 0; nt < 4; nt++)
                    mma_tf32(acc[mt][nt], af[mt][0], af[mt][1], af[mt][2], af[mt][3],
                             bf[nt][0], bf[nt][1]);
        }
    };

    // ---- prologue: tile 0 into stage 0 ----
    fetchA(0); fetchB(0);
    storeA(As[0]); storeB(Bs[0]);
    __syncthreads();

    int st = 0;
    for (int kk = 0; kk < K; kk += 16) {
        bool more = (kk + 16) < K;
        if (more) { fetchA(kk + 16); fetchB(kk + 16); }   // LDGs issue early
        compute(st);                                       // MMAs hide latency
        if (more) {
            storeA(As[st^1]); storeB(Bs[st^1]);
            __syncthreads();
            st ^= 1;
        }
    }

    // ---- epilogue ----
    #pragma unroll
    for (int mt = 0; mt < 4; mt++) {
        int mr0 = m0 + wm*64 + mt*16 + grp;   // rows mr0 and mr0+8
        int mr1 = mr0 + 8;
        float badd0 = 0.f, badd1 = 0.f;
        if (bias) { badd0 += bias[mr0]; badd1 += bias[mr1]; }
        if (film) { badd0 += film[b*M + mr0]; badd1 += film[b*M + mr1]; }
        #pragma unroll
        for (int nt = 0; nt < 4; nt++) {
            int nc = n0 + wn*32 + nt*8 + qd*2;
            long i0 = (long)mr0 * N + nc;
            long i1 = (long)mr1 * N + nc;
            float v00 = acc[mt][nt][0] * alpha + badd0;
            float v01 = acc[mt][nt][1] * alpha + badd0;
            float v10 = acc[mt][nt][2] * alpha + badd1;
            float v11 = acc[mt][nt][3] * alpha + badd1;
            if (addsrc) {
                v00 += addsrc[(long)b*sC + i0];
                v01 += addsrc[(long)b*sC + i0 + 1];
                v10 += addsrc[(long)b*sC + i1];
                v11 += addsrc[(long)b*sC + i1 + 1];
            }
            if (accumulate) {
                v00 += Cb[i0]; v01 += Cb[i0 + 1];
                v10 += Cb[i1]; v11 += Cb[i1 + 1];
            }
            *reinterpret_cast<float2*>(&Cb[i0]) = make_float2(v00, v01);
            *reinterpret_cast<float2*>(&Cb[i1]) = make_float2(v10, v11);
        }
    }
}

// ---------------- host launch ------------------------------------------------
extern "C" void kernel_launch(void* const* d_in, const int* in_sizes, int n_in,
                              void* d_out, int out_size) {
    const float* x          = (const float*)d_in[0];
    const float* noise_emb  = (const float*)d_in[1];
    const float* gn1_scale  = (const float*)d_in[2];
    const float* gn1_bias   = (const float*)d_in[3];
    const float* conv1_w    = (const float*)d_in[4];
    const float* conv1_b    = (const float*)d_in[5];
    const float* noise_w    = (const float*)d_in[6];
    const float* noise_b    = (const float*)d_in[7];
    const float* gn2_scale  = (const float*)d_in[8];
    const float* gn2_bias   = (const float*)d_in[9];
    const float* conv2_w    = (const float*)d_in[10];
    const float* conv2_b    = (const float*)d_in[11];
    const float* res_w      = (const float*)d_in[12];
    const float* res_b      = (const float*)d_in[13];
    const float* agn_scale  = (const float*)d_in[14];
    const float* agn_bias   = (const float*)d_in[15];
    const float* qkv_w      = (const float*)d_in[16];
    const float* out_w      = (const float*)d_in[17];
    const float* out_b      = (const float*)d_in[18];
    float* out = (float*)d_out;

    float *t0, *t1, *t2, *h, *qkv, *att, *film, *mean, *rstd;
    cudaGetSymbolAddress((void**)&t0,   g_t0);
    cudaGetSymbolAddress((void**)&t1,   g_t1);
    cudaGetSymbolAddress((void**)&t2,   g_t2);
    cudaGetSymbolAddress((void**)&h,    g_h);
    cudaGetSymbolAddress((void**)&qkv,  g_qkv);
    cudaGetSymbolAddress((void**)&att,  g_att);
    cudaGetSymbolAddress((void**)&film, g_film);
    cudaGetSymbolAddress((void**)&mean, g_mean);
    cudaGetSymbolAddress((void**)&rstd, g_rstd);

    const int ELTS = NB * CHW;            // 4194304
    const int EW_GRID = ELTS / 256;       // 16384

    // FiLM vector
    film_kernel<<<NB, NC>>>(noise_emb, noise_w, noise_b, film);

    // GN1 + SiLU
    gn_stats_kernel<<<NB*NG, 256>>>(x, mean, rstd);
    gn_apply_kernel<<<EW_GRID, 256>>>(x, mean, rstd, gn1_scale, gn1_bias, t0, 1);

    // conv1 (3x3, im2col GEMM) + FiLM add fused in epilogue
    gemm_tc_kernel<0,0,true><<<dim3(8,2,NB), 256>>>(
        conv1_w, t0, t1, NC, NHW, NC*9, 0, CHW, CHW, 1.f,
        conv1_b, film, nullptr, 0);

    // GN2 + SiLU
    gn_stats_kernel<<<NB*NG, 256>>>(t1, mean, rstd);
    gn_apply_kernel<<<EW_GRID, 256>>>(t1, mean, rstd, gn2_scale, gn2_bias, t2, 1);

    // residual 1x1 conv -> h
    gemm_tc_kernel<0,0,false><<<dim3(8,2,NB), 256>>>(
        res_w, x, h, NC, NHW, NC, 0, CHW, CHW, 1.f,
        res_b, nullptr, nullptr, 0);

    // conv2 (3x3) accumulates into h
    gemm_tc_kernel<0,0,true><<<dim3(8,2,NB), 256>>>(
        conv2_w, t2, h, NC, NHW, NC*9, 0, CHW, CHW, 1.f,
        conv2_b, nullptr, nullptr, 1);

    // attention GroupNorm (no SiLU) -> t0
    gn_stats_kernel<<<NB*NG, 256>>>(h, mean, rstd);
    gn_apply_kernel<<<EW_GRID, 256>>>(h, mean, rstd, agn_scale, agn_bias, t0, 0);

    // qkv 1x1 conv (no bias): [768x256] @ [256x1024]
    gemm_tc_kernel<0,0,false><<<dim3(8,6,NB), 256>>>(
        qkv_w, t0, qkv, 3*NC, NHW, NC, 0, CHW, (long)3*CHW, 1.f,
        nullptr, nullptr, nullptr, 0);

    // scores: S[b][s][t] = (1/16) * sum_d q[d][s] k[d][t]   (A is [K][M])
    gemm_tc_kernel<1,0,false><<<dim3(8,8,NB), 256>>>(
        qkv /*q*/, qkv + CHW /*k*/, att, NHW, NHW, NC,
        (long)3*CHW, (long)3*CHW, (long)NHW*NHW, 0.0625f,
        nullptr, nullptr, nullptr, 0);

    // softmax rows
    softmax_kernel<<<NB*NHW, 256>>>(att);

    // AV: O[b][d][s] = sum_t v[d][t] S[s][t]   (B is [N][K]) -> t2
    gemm_tc_kernel<0,1,false><<<dim3(8,2,NB), 256>>>(
        qkv + 2*CHW /*v*/, att, t2, NC, NHW, NHW,
        (long)3*CHW, (long)NHW*NHW, CHW, 1.f,
        nullptr, nullptr, nullptr, 0);

    // out 1x1 conv + bias + residual h -> d_out
    gemm_tc_kernel<0,0,false><<<dim3(8,2,NB), 256>>>(
        out_w, t2, out, NC, NHW, NC, 0, CHW, CHW, 1.f,
        out_b, nullptr, h, 0);
}

// round 6
// speedup vs baseline: 2.7769x; 1.1239x over previous
#include <cuda_runtime.h>
#include <math.h>
#include <stdint.h>

// Problem constants
#define NB   16          // batch
#define NC   256         // channels
#define NHW  1024        // H*W
#define NG   32          // groups
#define CHW  (NC*NHW)    // 262144 per-batch activation size
#define KC   (9*NC)      // 2304 conv GEMM depth

// ---------------- scratch (device globals; no runtime allocation) ----------
__device__ float g_t0[NB*CHW];
__device__ float g_t1[NB*CHW];
__device__ float g_t2[NB*CHW];
__device__ float g_h [NB*CHW];
__device__ float g_qkv[NB*3*CHW];         // 50 MB
__device__ float g_att[(long)NB*NHW*NHW]; // 67 MB
__device__ float g_film[NB*NC];
__device__ float g_mean[NB*NG];
__device__ float g_rstd[NB*NG];
__device__ float g_pw1[NC*KC];            // permuted conv1 weights
__device__ float g_pw2[NC*KC];            // permuted conv2 weights

// ---------------- weight permute: pw[m][r*256+ci] = w[m][ci*9+r] ------------
__global__ void permw_kernel(const float* __restrict__ w, float* __restrict__ pw) {
    int idx = blockIdx.x * 256 + threadIdx.x;   // covers 256*2304
    int m = idx / KC;
    int k = idx - m*KC;
    int r = k >> 8;
    int ci = k & 255;
    pw[idx] = w[m*KC + ci*9 + r];
}

// ---------------- FiLM: film[b][co] = emb[b] @ noise_w + noise_b -----------
__global__ void film_kernel(const float* __restrict__ emb,
                            const float* __restrict__ w,
                            const float* __restrict__ nb,
                            float* __restrict__ film) {
    int b = blockIdx.x;
    int co = threadIdx.x;
    __shared__ float e[NC];
    e[co] = emb[b*NC + co];
    __syncthreads();
    float acc = nb[co];
    #pragma unroll 8
    for (int k = 0; k < NC; k++) acc += e[k] * w[k*NC + co];
    film[b*NC + co] = acc;
}

// ---------------- GroupNorm stats ------------------------------------------
__global__ void gn_stats_kernel(const float* __restrict__ x,
                                float* __restrict__ mean,
                                float* __restrict__ rstd) {
    int bg = blockIdx.x;                      // 0..511
    const float* p = x + (long)bg * 8192;
    int t = threadIdx.x;
    float s = 0.f, s2 = 0.f;
    for (int i = t; i < 8192; i += 256) {
        float v = p[i];
        s += v; s2 += v*v;
    }
    __shared__ float sh[256], sh2[256];
    sh[t] = s; sh2[t] = s2;
    __syncthreads();
    for (int o = 128; o > 0; o >>= 1) {
        if (t < o) { sh[t] += sh[t+o]; sh2[t] += sh2[t+o]; }
        __syncthreads();
    }
    if (t == 0) {
        float m = sh[0] * (1.f/8192.f);
        float var = sh2[0] * (1.f/8192.f) - m*m;
        mean[bg] = m;
        rstd[bg] = rsqrtf(var + 1e-5f);
    }
}

// ---------------- GroupNorm apply (+optional SiLU) --------------------------
__global__ void gn_apply_kernel(const float* __restrict__ x,
                                const float* __restrict__ mean,
                                const float* __restrict__ rstd,
                                const float* __restrict__ scale,
                                const float* __restrict__ bias,
                                float* __restrict__ y,
                                int do_silu) {
    long idx = (long)blockIdx.x * 256 + threadIdx.x;
    int b   = (int)(idx >> 18);
    int ofs = (int)(idx & (CHW-1));
    int g   = ofs >> 13;
    int c   = ofs >> 10;
    int bg  = b*NG + g;
    float v = (x[idx] - mean[bg]) * rstd[bg] * scale[c] + bias[c];
    if (do_silu) v = v / (1.f + expf(-v));
    y[idx] = v;
}

// ---------------- Softmax over rows of 1024 ---------------------------------
__global__ void softmax_kernel(float* __restrict__ S) {
    long row = blockIdx.x;
    float* p = S + row * NHW;
    int t = threadIdx.x;
    float v[4];
    float mx = -1e30f;
    #pragma unroll
    for (int j = 0; j < 4; j++) { v[j] = p[t + j*256]; mx = fmaxf(mx, v[j]); }
    __shared__ float sh[256];
    sh[t] = mx; __syncthreads();
    for (int o = 128; o > 0; o >>= 1) { if (t < o) sh[t] = fmaxf(sh[t], sh[t+o]); __syncthreads(); }
    mx = sh[0]; __syncthreads();
    float s = 0.f;
    #pragma unroll
    for (int j = 0; j < 4; j++) { v[j] = expf(v[j] - mx); s += v[j]; }
    sh[t] = s; __syncthreads();
    for (int o = 128; o > 0; o >>= 1) { if (t < o) sh[t] += sh[t+o]; __syncthreads(); }
    float inv = 1.f / sh[0];
    #pragma unroll
    for (int j = 0; j < 4; j++) p[t + j*256] = v[j] * inv;
}

// ---------------- TF32 helpers ----------------------------------------------
__device__ __forceinline__ uint32_t to_tf32(float x) {
    uint32_t y;
    asm("cvt.rna.tf32.f32 %0, %1;" : "=r"(y) : "f"(x));
    return y;
}
__device__ __forceinline__ float to_tf32f(float x) {
    return __uint_as_float(to_tf32(x));
}

__device__ __forceinline__ void mma_tf32(float c[4], uint32_t a0, uint32_t a1,
                                         uint32_t a2, uint32_t a3,
                                         uint32_t b0, uint32_t b1) {
    asm volatile(
        "mma.sync.aligned.m16n8k8.row.col.f32.tf32.tf32.f32 "
        "{%0,%1,%2,%3}, {%4,%5,%6,%7}, {%8,%9}, {%0,%1,%2,%3};\n"
        : "+f"(c[0]), "+f"(c[1]), "+f"(c[2]), "+f"(c[3])
        : "r"(a0), "r"(a1), "r"(a2), "r"(a3), "r"(b0), "r"(b1));
}

// ---------------- Batched 128x128x16 TF32 tensor-core GEMM ------------------
// Double-buffered shared staging; one __syncthreads per k-tile.
// C[b][m][n] = alpha * sum_k A(m,k)*B(k,n) (+bias[m]) (+film[b][m])
//             (+addsrc[b][m][n]) (+= C if accumulate)
// TA=0: A row-major [M][K];  TA=1: A is [K][M] (lda = M)
// TB=0: B is [K][N];         TB=1: B is [N][K] (ldb = K)
// IMC : B is an image [Ci][32][32]; K = 9*Ci ordered k = r*256 + ci
//       (filter-tap-major; A must be the r-major permuted weight matrix).
//       Each 16-deep k-tile has constant r => constant (ih,iw) + predicate.
#define SAS 136   // shared strides; 136 mod 32 == 8 -> conflict-free frag loads
#define SBS 136

template<int TA, int TB, bool IMC>
__global__ __launch_bounds__(256)
void gemm_tc_kernel(const float* __restrict__ A,
                    const float* __restrict__ Bp,
                    float* __restrict__ Cp,
                    int M, int N, int K,
                    long sA, long sB, long sC,
                    float alpha,
                    const float* __restrict__ bias,
                    const float* __restrict__ film,
                    const float* __restrict__ addsrc,
                    int accumulate) {
    __shared__ float As[2][16*SAS];   // As[st][k][m], tf32 bits
    __shared__ float Bs[2][16*SBS];   // Bs[st][k][n], tf32 bits

    int b  = blockIdx.z;
    const float* Ab = A  + (long)b * sA;
    const float* Bb = Bp + (long)b * sB;
    float*       Cb = Cp + (long)b * sC;
    int m0 = blockIdx.y * 128;
    int n0 = blockIdx.x * 128;
    int t    = threadIdx.x;
    int lane = t & 31;
    int wid  = t >> 5;
    int wm   = wid & 1;          // warp m index (0..1) -> 64 rows
    int wn   = wid >> 1;         // warp n index (0..3) -> 32 cols
    int grp  = lane >> 2;        // 0..7
    int qd   = lane & 3;         // 0..3

    float acc[4][4][4];
    #pragma unroll
    for (int i = 0; i < 4; i++)
        #pragma unroll
        for (int j = 0; j < 4; j++)
            #pragma unroll
            for (int r = 0; r < 4; r++) acc[i][j][r] = 0.f;

    float aReg[8];
    float bReg[8];

    // im2col per-thread constants (valid when IMC)
    int ic_n  = t & 127;
    int ic_kr = t >> 7;                    // 0..1
    int ic_h  = (n0 + ic_n) >> 5;
    int ic_w  = (n0 + ic_n) & 31;

    auto fetchA = [&](int kk) {
        if (TA == 0) {
            #pragma unroll
            for (int r = 0; r < 2; r++) {
                int f = t + r*256;
                int m = f >> 2;
                int kq = (f & 3) << 2;
                float4 v = *reinterpret_cast<const float4*>(Ab + (long)(m0+m)*K + kk + kq);
                aReg[r*4+0] = v.x; aReg[r*4+1] = v.y;
                aReg[r*4+2] = v.z; aReg[r*4+3] = v.w;
            }
        } else {
            #pragma unroll
            for (int r = 0; r < 2; r++) {
                int f = t + r*256;
                int k = f >> 5;
                int mq = (f & 31) << 2;
                float4 v = *reinterpret_cast<const float4*>(Ab + (long)(kk+k)*M + m0 + mq);
                aReg[r*4+0] = v.x; aReg[r*4+1] = v.y;
                aReg[r*4+2] = v.z; aReg[r*4+3] = v.w;
            }
        }
    };
    auto storeA = [&](float* dst) {
        if (TA == 0) {
            #pragma unroll
            for (int r = 0; r < 2; r++) {
                int f = t + r*256;
                int m = f >> 2;
                int kq = (f & 3) << 2;
                dst[(kq+0)*SAS + m] = to_tf32f(aReg[r*4+0]);
                dst[(kq+1)*SAS + m] = to_tf32f(aReg[r*4+1]);
                dst[(kq+2)*SAS + m] = to_tf32f(aReg[r*4+2]);
                dst[(kq+3)*SAS + m] = to_tf32f(aReg[r*4+3]);
            }
        } else {
            #pragma unroll
            for (int r = 0; r < 2; r++) {
                int f = t + r*256;
                int k = f >> 5;
                int mq = (f & 31) << 2;
                float4 w;
                w.x = to_tf32f(aReg[r*4+0]); w.y = to_tf32f(aReg[r*4+1]);
                w.z = to_tf32f(aReg[r*4+2]); w.w = to_tf32f(aReg[r*4+3]);
                *reinterpret_cast<float4*>(&dst[k*SAS + mq]) = w;
            }
        }
    };
    auto fetchB = [&](int kk) {
        if (IMC) {
            // k = r*256 + ci; tile (16) never crosses an r boundary
            int r   = kk >> 8;
            int ci0 = (kk & 255) + ic_kr*8;
            int kh  = r / 3, kw = r - kh*3;
            int ih  = ic_h + kh - 1, iw = ic_w + kw - 1;
            bool ok = (ih >= 0 && ih < 32 && iw >= 0 && iw < 32);
            const float* src = Bb + (long)ci0*NHW + ih*32 + iw;
            #pragma unroll
            for (int j = 0; j < 8; j++)
                bReg[j] = ok ? src[j*NHW] : 0.f;
        } else if (TB == 0) {
            #pragma unroll
            for (int r = 0; r < 2; r++) {
                int f = t + r*256;
                int k = f >> 5;
                int nq = (f & 31) << 2;
                float4 v = *reinterpret_cast<const float4*>(Bb + (long)(kk+k)*N + n0 + nq);
                bReg[r*4+0] = v.x; bReg[r*4+1] = v.y;
                bReg[r*4+2] = v.z; bReg[r*4+3] = v.w;
            }
        } else {
            #pragma unroll
            for (int r = 0; r < 2; r++) {
                int f = t + r*256;
                int n = f >> 2;
                int kq = (f & 3) << 2;
                float4 v = *reinterpret_cast<const float4*>(Bb + (long)(n0+n)*K + kk + kq);
                bReg[r*4+0] = v.x; bReg[r*4+1] = v.y;
                bReg[r*4+2] = v.z; bReg[r*4+3] = v.w;
            }
        }
    };
    auto storeB = [&](float* dst) {
        if (IMC) {
            #pragma unroll
            for (int j = 0; j < 8; j++)
                dst[(ic_kr*8 + j)*SBS + ic_n] = to_tf32f(bReg[j]);
        } else if (TB == 0) {
            #pragma unroll
            for (int r = 0; r < 2; r++) {
                int f = t + r*256;
                int k = f >> 5;
                int nq = (f & 31) << 2;
                float4 w;
                w.x = to_tf32f(bReg[r*4+0]); w.y = to_tf32f(bReg[r*4+1]);
                w.z = to_tf32f(bReg[r*4+2]); w.w = to_tf32f(bReg[r*4+3]);
                *reinterpret_cast<float4*>(&dst[k*SBS + nq]) = w;
            }
        } else {
            #pragma unroll
            for (int r = 0; r < 2; r++) {
                int f = t + r*256;
                int n = f >> 2;
                int kq = (f & 3) << 2;
                dst[(kq+0)*SBS + n] = to_tf32f(bReg[r*4+0]);
                dst[(kq+1)*SBS + n] = to_tf32f(bReg[r*4+1]);
                dst[(kq+2)*SBS + n] = to_tf32f(bReg[r*4+2]);
                dst[(kq+3)*SBS + n] = to_tf32f(bReg[r*4+3]);
            }
        }
    };
    auto compute = [&](int st) {
        const uint32_t* AsU = reinterpret_cast<const uint32_t*>(As[st]);
        const uint32_t* BsU = reinterpret_cast<const uint32_t*>(Bs[st]);
        #pragma unroll
        for (int ks = 0; ks < 16; ks += 8) {
            uint32_t af[4][4];
            #pragma unroll
            for (int mt = 0; mt < 4; mt++) {
                int mb = wm*64 + mt*16 + grp;
                af[mt][0] = AsU[(ks+qd)*SAS + mb];
                af[mt][1] = AsU[(ks+qd)*SAS + mb + 8];
                af[mt][2] = AsU[(ks+4+qd)*SAS + mb];
                af[mt][3] = AsU[(ks+4+qd)*SAS + mb + 8];
            }
            uint32_t bf[4][2];
            #pragma unroll
            for (int nt = 0; nt < 4; nt++) {
                int nb = wn*32 + nt*8 + grp;
                bf[nt][0] = BsU[(ks+qd)*SBS + nb];
                bf[nt][1] = BsU[(ks+4+qd)*SBS + nb];
            }
            #pragma unroll
            for (int mt = 0; mt < 4; mt++)
                #pragma unroll
                for (int nt = 0; nt < 4; nt++)
                    mma_tf32(acc[mt][nt], af[mt][0], af[mt][1], af[mt][2], af[mt][3],
                             bf[nt][0], bf[nt][1]);
        }
    };

    // ---- prologue ----
    fetchA(0); fetchB(0);
    storeA(As[0]); storeB(Bs[0]);
    __syncthreads();

    int st = 0;
    for (int kk = 0; kk < K; kk += 16) {
        bool more = (kk + 16) < K;
        if (more) { fetchA(kk + 16); fetchB(kk + 16); }
        compute(st);
        if (more) {
            storeA(As[st^1]); storeB(Bs[st^1]);
            __syncthreads();
            st ^= 1;
        }
    }

    // ---- epilogue ----
    #pragma unroll
    for (int mt = 0; mt < 4; mt++) {
        int mr0 = m0 + wm*64 + mt*16 + grp;
        int mr1 = mr0 + 8;
        float badd0 = 0.f, badd1 = 0.f;
        if (bias) { badd0 += bias[mr0]; badd1 += bias[mr1]; }
        if (film) { badd0 += film[b*M + mr0]; badd1 += film[b*M + mr1]; }
        #pragma unroll
        for (int nt = 0; nt < 4; nt++) {
            int nc = n0 + wn*32 + nt*8 + qd*2;
            long i0 = (long)mr0 * N + nc;
            long i1 = (long)mr1 * N + nc;
            float v00 = acc[mt][nt][0] * alpha + badd0;
            float v01 = acc[mt][nt][1] * alpha + badd0;
            float v10 = acc[mt][nt][2] * alpha + badd1;
            float v11 = acc[mt][nt][3] * alpha + badd1;
            if (addsrc) {
                v00 += addsrc[(long)b*sC + i0];
                v01 += addsrc[(long)b*sC + i0 + 1];
                v10 += addsrc[(long)b*sC + i1];
                v11 += addsrc[(long)b*sC + i1 + 1];
            }
            if (accumulate) {
                v00 += Cb[i0]; v01 += Cb[i0 + 1];
                v10 += Cb[i1]; v11 += Cb[i1 + 1];
            }
            *reinterpret_cast<float2*>(&Cb[i0]) = make_float2(v00, v01);
            *reinterpret_cast<float2*>(&Cb[i1]) = make_float2(v10, v11);
        }
    }
}

// ---------------- host launch ------------------------------------------------
extern "C" void kernel_launch(void* const* d_in, const int* in_sizes, int n_in,
                              void* d_out, int out_size) {
    const float* x          = (const float*)d_in[0];
    const float* noise_emb  = (const float*)d_in[1];
    const float* gn1_scale  = (const float*)d_in[2];
    const float* gn1_bias   = (const float*)d_in[3];
    const float* conv1_w    = (const float*)d_in[4];
    const float* conv1_b    = (const float*)d_in[5];
    const float* noise_w    = (const float*)d_in[6];
    const float* noise_b    = (const float*)d_in[7];
    const float* gn2_scale  = (const float*)d_in[8];
    const float* gn2_bias   = (const float*)d_in[9];
    const float* conv2_w    = (const float*)d_in[10];
    const float* conv2_b    = (const float*)d_in[11];
    const float* res_w      = (const float*)d_in[12];
    const float* res_b      = (const float*)d_in[13];
    const float* agn_scale  = (const float*)d_in[14];
    const float* agn_bias   = (const float*)d_in[15];
    const float* qkv_w      = (const float*)d_in[16];
    const float* out_w      = (const float*)d_in[17];
    const float* out_b      = (const float*)d_in[18];
    float* out = (float*)d_out;

    float *t0, *t1, *t2, *h, *qkv, *att, *film, *mean, *rstd, *pw1, *pw2;
    cudaGetSymbolAddress((void**)&t0,   g_t0);
    cudaGetSymbolAddress((void**)&t1,   g_t1);
    cudaGetSymbolAddress((void**)&t2,   g_t2);
    cudaGetSymbolAddress((void**)&h,    g_h);
    cudaGetSymbolAddress((void**)&qkv,  g_qkv);
    cudaGetSymbolAddress((void**)&att,  g_att);
    cudaGetSymbolAddress((void**)&film, g_film);
    cudaGetSymbolAddress((void**)&mean, g_mean);
    cudaGetSymbolAddress((void**)&rstd, g_rstd);
    cudaGetSymbolAddress((void**)&pw1,  g_pw1);
    cudaGetSymbolAddress((void**)&pw2,  g_pw2);

    const int ELTS = NB * CHW;            // 4194304
    const int EW_GRID = ELTS / 256;       // 16384
    const int PW_GRID = NC*KC/256;        // 2304

    // permute conv weights to r-major k layout
    permw_kernel<<<PW_GRID, 256>>>(conv1_w, pw1);
    permw_kernel<<<PW_GRID, 256>>>(conv2_w, pw2);

    // FiLM vector
    film_kernel<<<NB, NC>>>(noise_emb, noise_w, noise_b, film);

    // GN1 + SiLU
    gn_stats_kernel<<<NB*NG, 256>>>(x, mean, rstd);
    gn_apply_kernel<<<EW_GRID, 256>>>(x, mean, rstd, gn1_scale, gn1_bias, t0, 1);

    // conv1 (3x3, r-major im2col GEMM) + FiLM add fused
    gemm_tc_kernel<0,0,true><<<dim3(8,2,NB), 256>>>(
        pw1, t0, t1, NC, NHW, KC, 0, CHW, CHW, 1.f,
        conv1_b, film, nullptr, 0);

    // GN2 + SiLU
    gn_stats_kernel<<<NB*NG, 256>>>(t1, mean, rstd);
    gn_apply_kernel<<<EW_GRID, 256>>>(t1, mean, rstd, gn2_scale, gn2_bias, t2, 1);

    // residual 1x1 conv -> h
    gemm_tc_kernel<0,0,false><<<dim3(8,2,NB), 256>>>(
        res_w, x, h, NC, NHW, NC, 0, CHW, CHW, 1.f,
        res_b, nullptr, nullptr, 0);

    // conv2 (3x3) accumulates into h
    gemm_tc_kernel<0,0,true><<<dim3(8,2,NB), 256>>>(
        pw2, t2, h, NC, NHW, KC, 0, CHW, CHW, 1.f,
        conv2_b, nullptr, nullptr, 1);

    // attention GroupNorm (no SiLU) -> t0
    gn_stats_kernel<<<NB*NG, 256>>>(h, mean, rstd);
    gn_apply_kernel<<<EW_GRID, 256>>>(h, mean, rstd, agn_scale, agn_bias, t0, 0);

    // qkv 1x1 conv (no bias): [768x256] @ [256x1024]
    gemm_tc_kernel<0,0,false><<<dim3(8,6,NB), 256>>>(
        qkv_w, t0, qkv, 3*NC, NHW, NC, 0, CHW, (long)3*CHW, 1.f,
        nullptr, nullptr, nullptr, 0);

    // scores: S[b][s][t] = (1/16) * sum_d q[d][s] k[d][t]   (A is [K][M])
    gemm_tc_kernel<1,0,false><<<dim3(8,8,NB), 256>>>(
        qkv /*q*/, qkv + CHW /*k*/, att, NHW, NHW, NC,
        (long)3*CHW, (long)3*CHW, (long)NHW*NHW, 0.0625f,
        nullptr, nullptr, nullptr, 0);

    // softmax rows
    softmax_kernel<<<NB*NHW, 256>>>(att);

    // AV: O[b][d][s] = sum_t v[d][t] S[s][t]   (B is [N][K]) -> t2
    gemm_tc_kernel<0,1,false><<<dim3(8,2,NB), 256>>>(
        qkv + 2*CHW /*v*/, att, t2, NC, NHW, NHW,
        (long)3*CHW, (long)NHW*NHW, CHW, 1.f,
        nullptr, nullptr, nullptr, 0);

    // out 1x1 conv + bias + residual h -> d_out
    gemm_tc_kernel<0,0,false><<<dim3(8,2,NB), 256>>>(
        out_w, t2, out, NC, NHW, NC, 0, CHW, CHW, 1.f,
        out_b, nullptr, h, 0);
}

// round 8
// speedup vs baseline: 2.9569x; 1.0648x over previous
#include <cuda_runtime.h>
#include <math.h>
#include <stdint.h>

// Problem constants
#define NB   16          // batch
#define NC   256         // channels
#define NHW  1024        // H*W
#define NG   32          // groups
#define CHW  (NC*NHW)    // 262144 per-batch activation size
#define KC   (9*NC)      // 2304 conv GEMM depth

// ---------------- scratch (device globals; no runtime allocation) ----------
__device__ float g_t0[NB*CHW];
__device__ float g_t1[NB*CHW];
__device__ float g_t2[NB*CHW];
__device__ float g_h [NB*CHW];
__device__ float g_qkv[NB*3*CHW];         // 50 MB
__device__ float g_att[(long)NB*NHW*NHW]; // 67 MB
__device__ float g_film[NB*NC];
__device__ float g_mean[NB*NG];
__device__ float g_rstd[NB*NG];
__device__ float g_pw1[NC*KC];            // permuted+tf32 conv1 weights
__device__ float g_pw2[NC*KC];            // permuted+tf32 conv2 weights
__device__ float g_wq[3*NC*NC];           // tf32 qkv weights
__device__ float g_wr[NC*NC];             // tf32 res weights
__device__ float g_wo[NC*NC];             // tf32 out weights
__device__ float g_xc[NB*CHW];            // tf32 copy of x

// ---------------- TF32 helpers ----------------------------------------------
__device__ __forceinline__ uint32_t to_tf32(float x) {
    uint32_t y;
    asm("cvt.rna.tf32.f32 %0, %1;" : "=r"(y) : "f"(x));
    return y;
}
__device__ __forceinline__ float to_tf32f(float x) {
    return __uint_as_float(to_tf32(x));
}

// ---------------- cp.async helpers ------------------------------------------
__device__ __forceinline__ void cp16(uint32_t dst, const float* src) {
    asm volatile("cp.async.cg.shared.global [%0], [%1], 16;\n"
                 :: "r"(dst), "l"(src));
}
__device__ __forceinline__ void cp4z(uint32_t dst, const float* src, int sz) {
    asm volatile("cp.async.ca.shared.global [%0], [%1], 4, %2;\n"
                 :: "r"(dst), "l"(src), "r"(sz));
}
__device__ __forceinline__ void cp_commit() {
    asm volatile("cp.async.commit_group;\n");
}
__device__ __forceinline__ void cp_wait0() {
    asm volatile("cp.async.wait_group 0;\n");
}

// ---------------- weight permute+convert: pw[m][r*256+ci] = w[m][ci*9+r] ----
__global__ void permw_kernel(const float* __restrict__ w, float* __restrict__ pw) {
    int idx = blockIdx.x * 256 + threadIdx.x;   // covers 256*2304
    int m = idx / KC;
    int k = idx - m*KC;
    int r = k >> 8;
    int ci = k & 255;
    pw[idx] = to_tf32f(w[m*KC + ci*9 + r]);
}

// ---------------- elementwise tf32 convert ----------------------------------
__global__ void cvt_kernel(const float* __restrict__ in, float* __restrict__ out) {
    long idx = (long)blockIdx.x * 256 + threadIdx.x;
    out[idx] = to_tf32f(in[idx]);
}

// ---------------- FiLM: film[b][co] = emb[b] @ noise_w + noise_b -----------
__global__ void film_kernel(const float* __restrict__ emb,
                            const float* __restrict__ w,
                            const float* __restrict__ nb,
                            float* __restrict__ film) {
    int b = blockIdx.x;
    int co = threadIdx.x;
    __shared__ float e[NC];
    e[co] = emb[b*NC + co];
    __syncthreads();
    float acc = nb[co];
    #pragma unroll 8
    for (int k = 0; k < NC; k++) acc += e[k] * w[k*NC + co];
    film[b*NC + co] = acc;
}

// ---------------- GroupNorm stats ------------------------------------------
__global__ void gn_stats_kernel(const float* __restrict__ x,
                                float* __restrict__ mean,
                                float* __restrict__ rstd) {
    int bg = blockIdx.x;                      // 0..511
    const float* p = x + (long)bg * 8192;
    int t = threadIdx.x;
    float s = 0.f, s2 = 0.f;
    for (int i = t; i < 8192; i += 256) {
        float v = p[i];
        s += v; s2 += v*v;
    }
    __shared__ float sh[256], sh2[256];
    sh[t] = s; sh2[t] = s2;
    __syncthreads();
    for (int o = 128; o > 0; o >>= 1) {
        if (t < o) { sh[t] += sh[t+o]; sh2[t] += sh2[t+o]; }
        __syncthreads();
    }
    if (t == 0) {
        float m = sh[0] * (1.f/8192.f);
        float var = sh2[0] * (1.f/8192.f) - m*m;
        mean[bg] = m;
        rstd[bg] = rsqrtf(var + 1e-5f);
    }
}

// ---------------- GroupNorm apply (+optional SiLU), tf32-rounded output -----
__global__ void gn_apply_kernel(const float* __restrict__ x,
                                const float* __restrict__ mean,
                                const float* __restrict__ rstd,
                                const float* __restrict__ scale,
                                const float* __restrict__ bias,
                                float* __restrict__ y,
                                int do_silu) {
    long idx = (long)blockIdx.x * 256 + threadIdx.x;
    int b   = (int)(idx >> 18);
    int ofs = (int)(idx & (CHW-1));
    int g   = ofs >> 13;
    int c   = ofs >> 10;
    int bg  = b*NG + g;
    float v = (x[idx] - mean[bg]) * rstd[bg] * scale[c] + bias[c];
    if (do_silu) v = v / (1.f + expf(-v));
    y[idx] = to_tf32f(v);   // output feeds a GEMM only
}

// ---------------- Softmax over rows of 1024, tf32-rounded output ------------
__global__ void softmax_kernel(float* __restrict__ S) {
    long row = blockIdx.x;
    float* p = S + row * NHW;
    int t = threadIdx.x;
    float v[4];
    float mx = -1e30f;
    #pragma unroll
    for (int j = 0; j < 4; j++) { v[j] = p[t + j*256]; mx = fmaxf(mx, v[j]); }
    __shared__ float sh[256];
    sh[t] = mx; __syncthreads();
    for (int o = 128; o > 0; o >>= 1) { if (t < o) sh[t] = fmaxf(sh[t], sh[t+o]); __syncthreads(); }
    mx = sh[0]; __syncthreads();
    float s = 0.f;
    #pragma unroll
    for (int j = 0; j < 4; j++) { v[j] = expf(v[j] - mx); s += v[j]; }
    sh[t] = s; __syncthreads();
    for (int o = 128; o > 0; o >>= 1) { if (t < o) sh[t] += sh[t+o]; __syncthreads(); }
    float inv = 1.f / sh[0];
    #pragma unroll
    for (int j = 0; j < 4; j++) p[t + j*256] = to_tf32f(v[j] * inv);
}

__device__ __forceinline__ void mma_tf32(float c[4], uint32_t a0, uint32_t a1,
                                         uint32_t a2, uint32_t a3,
                                         uint32_t b0, uint32_t b1) {
    asm volatile(
        "mma.sync.aligned.m16n8k8.row.col.f32.tf32.tf32.f32 "
        "{%0,%1,%2,%3}, {%4,%5,%6,%7}, {%8,%9}, {%0,%1,%2,%3};\n"
        : "+f"(c[0]), "+f"(c[1]), "+f"(c[2]), "+f"(c[3])
        : "r"(a0), "r"(a1), "r"(a2), "r"(a3), "r"(b0), "r"(b1));
}

// ---------------- Batched 128x128x16 TF32 GEMM, cp.async pipelined ----------
// All inputs are PRE-ROUNDED tf32 bit patterns; no conversion in kernel.
// C[b][m][n] = alpha * sum_k A(m,k)*B(k,n) (+bias[m]) (+film[b][m])
//             (+addsrc[b][m][n]) (+= C if accumulate) (tf32-round if RND)
// TA=0: A row-major [M][K], smem layout [m][k] stride 20
// TA=1: A is [K][M],        smem layout [k][m] stride 136
// TB=0: B is [K][N],        smem layout [k][n] stride 136
// TB=1: B is [N][K],        smem layout [n][k] stride 20
// IMC : B image [Ci][32][32], K=9*Ci with k=r*256+ci (tap-major); [k][n] 136.
#define SA0 20
#define SKM 136
#define SNK 20
#define ASZ 2560            // max(128*20, 16*136)
#define BSZ 2560            // max(16*136, 128*20)
#define STG (ASZ+BSZ)       // floats per stage

template<int TA, int TB, bool IMC, int RND>
__global__ __launch_bounds__(256)
void gemm_tc_kernel(const float* __restrict__ A,
                    const float* __restrict__ Bp,
                    float* __restrict__ Cp,
                    int M, int N, int K,
                    long sA, long sB, long sC,
                    float alpha,
                    const float* __restrict__ bias,
                    const float* __restrict__ film,
                    const float* __restrict__ addsrc,
                    int accumulate) {
    __shared__ __align__(16) float smem[2][STG];

    int b  = blockIdx.z;
    const float* Ab = A  + (long)b * sA;
    const float* Bb = Bp + (long)b * sB;
    float*       Cb = Cp + (long)b * sC;
    int m0 = blockIdx.y * 128;
    int n0 = blockIdx.x * 128;
    int t    = threadIdx.x;
    int lane = t & 31;
    int wid  = t >> 5;
    int wm   = wid & 1;          // warp m index (0..1) -> 64 rows
    int wn   = wid >> 1;         // warp n index (0..3) -> 32 cols
    int grp  = lane >> 2;        // 0..7
    int qd   = lane & 3;         // 0..3

    uint32_t sb = (uint32_t)__cvta_generic_to_shared(&smem[0][0]);

    float acc[4][4][4];
    #pragma unroll
    for (int i = 0; i < 4; i++)
        #pragma unroll
        for (int j = 0; j < 4; j++)
            #pragma unroll
            for (int r = 0; r < 4; r++) acc[i][j][r] = 0.f;

    // im2col per-thread constants
    int ic_n  = t & 127;
    int ic_kr = t >> 7;                    // 0..1
    int ic_h  = (n0 + ic_n) >> 5;
    int ic_w  = (n0 + ic_n) & 31;

    auto prefA = [&](int kk, int s) {
        uint32_t ab = sb + (uint32_t)(s*STG)*4u;
        if (TA == 0) {
            #pragma unroll
            for (int r = 0; r < 2; r++) {
                int c = t + r*256;
                int m = c >> 2;
                int kq = (c & 3) << 2;
                cp16(ab + (uint32_t)(m*SA0 + kq)*4u,
                     Ab + (long)(m0+m)*K + kk + kq);
            }
        } else {
            #pragma unroll
            for (int r = 0; r < 2; r++) {
                int c = t + r*256;
                int k = c >> 5;
                int mq = (c & 31) << 2;
                cp16(ab + (uint32_t)(k*SKM + mq)*4u,
                     Ab + (long)(kk+k)*M + m0 + mq);
            }
        }
    };
    auto prefB = [&](int kk, int s) {
        uint32_t bbase = sb + (uint32_t)(s*STG + ASZ)*4u;
        if (IMC) {
            int r   = kk >> 8;            // constant tap for this tile
            int ci0 = (kk & 255) + ic_kr*8;
            int kh  = r / 3, kw = r - kh*3;
            int ih  = ic_h + kh - 1, iw = ic_w + kw - 1;
            bool ok = (ih >= 0 && ih < 32 && iw >= 0 && iw < 32);
            const float* src = ok ? (Bb + (long)ci0*NHW + ih*32 + iw) : Bb;
            int sz = ok ? 4 : 0;
            #pragma unroll
            for (int j = 0; j < 8; j++)
                cp4z(bbase + (uint32_t)((ic_kr*8 + j)*SKM + ic_n)*4u,
                     src + j*NHW, sz);
        } else if (TB == 0) {
            #pragma unroll
            for (int r = 0; r < 2; r++) {
                int c = t + r*256;
                int k = c >> 5;
                int nq = (c & 31) << 2;
                cp16(bbase + (uint32_t)(k*SKM + nq)*4u,
                     Bb + (long)(kk+k)*N + n0 + nq);
            }
        } else {
            #pragma unroll
            for (int r = 0; r < 2; r++) {
                int c = t + r*256;
                int n = c >> 2;
                int kq = (c & 3) << 2;
                cp16(bbase + (uint32_t)(n*SNK + kq)*4u,
                     Bb + (long)(n0+n)*K + kk + kq);
            }
        }
    };
    auto compute = [&](int s) {
        const uint32_t* AsU = reinterpret_cast<const uint32_t*>(&smem[s][0]);
        const uint32_t* BsU = reinterpret_cast<const uint32_t*>(&smem[s][ASZ]);
        #pragma unroll
        for (int ks = 0; ks < 16; ks += 8) {
            uint32_t af[4][4];
            #pragma unroll
            for (int mt = 0; mt < 4; mt++) {
                int mb = wm*64 + mt*16 + grp;
                if (TA == 0) {
                    af[mt][0] = AsU[mb*SA0 + ks + qd];
                    af[mt][1] = AsU[(mb+8)*SA0 + ks + qd];
                    af[mt][2] = AsU[mb*SA0 + ks + 4 + qd];
                    af[mt][3] = AsU[(mb+8)*SA0 + ks + 4 + qd];
                } else {
                    af[mt][0] = AsU[(ks+qd)*SKM + mb];
                    af[mt][1] = AsU[(ks+qd)*SKM + mb + 8];
                    af[mt][2] = AsU[(ks+4+qd)*SKM + mb];
                    af[mt][3] = AsU[(ks+4+qd)*SKM + mb + 8];
                }
            }
            uint32_t bf[4][2];
            #pragma unroll
            for (int nt = 0; nt < 4; nt++) {
                int nb = wn*32 + nt*8 + grp;
                if (TB == 1) {
                    bf[nt][0] = BsU[nb*SNK + ks + qd];
                    bf[nt][1] = BsU[nb*SNK + ks + 4 + qd];
                } else {
                    bf[nt][0] = BsU[(ks+qd)*SKM + nb];
                    bf[nt][1] = BsU[(ks+4+qd)*SKM + nb];
                }
            }
            #pragma unroll
            for (int mt = 0; mt < 4; mt++)
                #pragma unroll
                for (int nt = 0; nt < 4; nt++)
                    mma_tf32(acc[mt][nt], af[mt][0], af[mt][1], af[mt][2], af[mt][3],
                             bf[nt][0], bf[nt][1]);
        }
    };

    // ---- pipelined mainloop ----
    prefA(0, 0); prefB(0, 0); cp_commit();
    int st = 0;
    for (int kk = 0; kk < K; kk += 16) {
        cp_wait0();
        __syncthreads();
        if (kk + 16 < K) { prefA(kk+16, st^1); prefB(kk+16, st^1); cp_commit(); }
        compute(st);
        st ^= 1;
    }

    // ---- epilogue ----
    #pragma unroll
    for (int mt = 0; mt < 4; mt++) {
        int mr0 = m0 + wm*64 + mt*16 + grp;
        int mr1 = mr0 + 8;
        float badd0 = 0.f, badd1 = 0.f;
        if (bias) { badd0 += bias[mr0]; badd1 += bias[mr1]; }
        if (film) { badd0 += film[b*M + mr0]; badd1 += film[b*M + mr1]; }
        #pragma unroll
        for (int nt = 0; nt < 4; nt++) {
            int nc = n0 + wn*32 + nt*8 + qd*2;
            long i0 = (long)mr0 * N + nc;
            long i1 = (long)mr1 * N + nc;
            float v00 = acc[mt][nt][0] * alpha + badd0;
            float v01 = acc[mt][nt][1] * alpha + badd0;
            float v10 = acc[mt][nt][2] * alpha + badd1;
            float v11 = acc[mt][nt][3] * alpha + badd1;
            if (addsrc) {
                v00 += addsrc[(long)b*sC + i0];
                v01 += addsrc[(long)b*sC + i0 + 1];
                v10 += addsrc[(long)b*sC + i1];
                v11 += addsrc[(long)b*sC + i1 + 1];
            }
            if (accumulate) {
                v00 += Cb[i0]; v01 += Cb[i0 + 1];
                v10 += Cb[i1]; v11 += Cb[i1 + 1];
            }
            if (RND) {
                v00 = to_tf32f(v00); v01 = to_tf32f(v01);
                v10 = to_tf32f(v10); v11 = to_tf32f(v11);
            }
            *reinterpret_cast<float2*>(&Cb[i0]) = make_float2(v00, v01);
            *reinterpret_cast<float2*>(&Cb[i1]) = make_float2(v10, v11);
        }
    }
}

// ---------------- host launch ------------------------------------------------
extern "C" void kernel_launch(void* const* d_in, const int* in_sizes, int n_in,
                              void* d_out, int out_size) {
    const float* x          = (const float*)d_in[0];
    const float* noise_emb  = (const float*)d_in[1];
    const float* gn1_scale  = (const float*)d_in[2];
    const float* gn1_bias   = (const float*)d_in[3];
    const float* conv1_w    = (const float*)d_in[4];
    const float* conv1_b    = (const float*)d_in[5];
    const float* noise_w    = (const float*)d_in[6];
    const float* noise_b    = (const float*)d_in[7];
    const float* gn2_scale  = (const float*)d_in[8];
    const float* gn2_bias   = (const float*)d_in[9];
    const float* conv2_w    = (const float*)d_in[10];
    const float* conv2_b    = (const float*)d_in[11];
    const float* res_w      = (const float*)d_in[12];
    const float* res_b      = (const float*)d_in[13];
    const float* agn_scale  = (const float*)d_in[14];
    const float* agn_bias   = (const float*)d_in[15];
    const float* qkv_w      = (const float*)d_in[16];
    const float* out_w      = (const float*)d_in[17];
    const float* out_b      = (const float*)d_in[18];
    float* out = (float*)d_out;

    float *t0, *t1, *t2, *h, *qkv, *att, *film, *mean, *rstd;
    float *pw1, *pw2, *wq, *wr, *wo, *xc;
    cudaGetSymbolAddress((void**)&t0,   g_t0);
    cudaGetSymbolAddress((void**)&t1,   g_t1);
    cudaGetSymbolAddress((void**)&t2,   g_t2);
    cudaGetSymbolAddress((void**)&h,    g_h);
    cudaGetSymbolAddress((void**)&qkv,  g_qkv);
    cudaGetSymbolAddress((void**)&att,  g_att);
    cudaGetSymbolAddress((void**)&film, g_film);
    cudaGetSymbolAddress((void**)&mean, g_mean);
    cudaGetSymbolAddress((void**)&rstd, g_rstd);
    cudaGetSymbolAddress((void**)&pw1,  g_pw1);
    cudaGetSymbolAddress((void**)&pw2,  g_pw2);
    cudaGetSymbolAddress((void**)&wq,   g_wq);
    cudaGetSymbolAddress((void**)&wr,   g_wr);
    cudaGetSymbolAddress((void**)&wo,   g_wo);
    cudaGetSymbolAddress((void**)&xc,   g_xc);

    const int ELTS = NB * CHW;            // 4194304
    const int EW_GRID = ELTS / 256;       // 16384
    const int PW_GRID = NC*KC/256;        // 2304

    // one-shot weight/input conversions (tf32 bit patterns)
    permw_kernel<<<PW_GRID, 256>>>(conv1_w, pw1);
    permw_kernel<<<PW_GRID, 256>>>(conv2_w, pw2);
    cvt_kernel<<<3*NC*NC/256, 256>>>(qkv_w, wq);
    cvt_kernel<<<NC*NC/256, 256>>>(res_w, wr);
    cvt_kernel<<<NC*NC/256, 256>>>(out_w, wo);
    cvt_kernel<<<EW_GRID, 256>>>(x, xc);

    // FiLM vector
    film_kernel<<<NB, NC>>>(noise_emb, noise_w, noise_b, film);

    // GN1 + SiLU (tf32 out)
    gn_stats_kernel<<<NB*NG, 256>>>(x, mean, rstd);
    gn_apply_kernel<<<EW_GRID, 256>>>(x, mean, rstd, gn1_scale, gn1_bias, t0, 1);

    // conv1 (3x3, tap-major im2col GEMM) + FiLM add fused
    gemm_tc_kernel<0,0,true,0><<<dim3(8,2,NB), 256>>>(
        pw1, t0, t1, NC, NHW, KC, 0, CHW, CHW, 1.f,
        conv1_b, film, nullptr, 0);

    // GN2 + SiLU (tf32 out)
    gn_stats_kernel<<<NB*NG, 256>>>(t1, mean, rstd);
    gn_apply_kernel<<<EW_GRID, 256>>>(t1, mean, rstd, gn2_scale, gn2_bias, t2, 1);

    // residual 1x1 conv -> h (fp32 out)
    gemm_tc_kernel<0,0,false,0><<<dim3(8,2,NB), 256>>>(
        wr, xc, h, NC, NHW, NC, 0, CHW, CHW, 1.f,
        res_b, nullptr, nullptr, 0);

    // conv2 (3x3) accumulates into h (fp32)
    gemm_tc_kernel<0,0,true,0><<<dim3(8,2,NB), 256>>>(
        pw2, t2, h, NC, NHW, KC, 0, CHW, CHW, 1.f,
        conv2_b, nullptr, nullptr, 1);

    // attention GroupNorm (no SiLU, tf32 out) -> t0
    gn_stats_kernel<<<NB*NG, 256>>>(h, mean, rstd);
    gn_apply_kernel<<<EW_GRID, 256>>>(h, mean, rstd, agn_scale, agn_bias, t0, 0);

    // qkv 1x1 conv (no bias), output tf32-rounded
    gemm_tc_kernel<0,0,false,1><<<dim3(8,6,NB), 256>>>(
        wq, t0, qkv, 3*NC, NHW, NC, 0, CHW, (long)3*CHW, 1.f,
        nullptr, nullptr, nullptr, 0);

    // scores: S[b][s][t] = (1/16) * sum_d q[d][s] k[d][t]   (A is [K][M])
    gemm_tc_kernel<1,0,false,0><<<dim3(8,8,NB), 256>>>(
        qkv /*q*/, qkv + CHW /*k*/, att, NHW, NHW, NC,
        (long)3*CHW, (long)3*CHW, (long)NHW*NHW, 0.0625f,
        nullptr, nullptr, nullptr, 0);

    // softmax rows (tf32 out)
    softmax_kernel<<<NB*NHW, 256>>>(att);

    // AV: O[b][d][s] = sum_t v[d][t] S[s][t] (B is [N][K]), tf32-rounded out
    gemm_tc_kernel<0,1,false,1><<<dim3(8,2,NB), 256>>>(
        qkv + 2*CHW /*v*/, att, t2, NC, NHW, NHW,
        (long)3*CHW, (long)NHW*NHW, CHW, 1.f,
        nullptr, nullptr, nullptr, 0);

    // out 1x1 conv + bias + residual h -> d_out (fp32)
    gemm_tc_kernel<0,0,false,0><<<dim3(8,2,NB), 256>>>(
        wo, t2, out, NC, NHW, NC, 0, CHW, CHW, 1.f,
        out_b, nullptr, h, 0);
}

// round 9
// speedup vs baseline: 3.0730x; 1.0393x over previous
#include <cuda_runtime.h>
#include <math.h>
#include <stdint.h>

// Problem constants
#define NB   16          // batch
#define NC   256         // channels
#define NHW  1024        // H*W
#define NG   32          // groups
#define CHW  (NC*NHW)    // 262144 per-batch activation size
#define KC   (9*NC)      // 2304 conv GEMM depth

// ---------------- scratch (device globals; no runtime allocation) ----------
__device__ float g_t0[NB*CHW];
__device__ float g_t1[NB*CHW];
__device__ float g_t2[NB*CHW];
__device__ float g_h [NB*CHW];
__device__ float g_qkv[NB*3*CHW];         // 50 MB
__device__ float g_att[(long)NB*NHW*NHW]; // 67 MB
__device__ float g_film[NB*NC];
__device__ float g_mean[NB*NG];
__device__ float g_rstd[NB*NG];
__device__ float g_pw1[NC*KC];            // permuted+tf32 conv1 weights
__device__ float g_pw2[NC*KC];            // permuted+tf32 conv2 weights
__device__ float g_wq[3*NC*NC];           // tf32 qkv weights
__device__ float g_wr[NC*NC];             // tf32 res weights
__device__ float g_wo[NC*NC];             // tf32 out weights
__device__ float g_xc[NB*CHW];            // tf32 copy of x

// ---------------- TF32 helpers ----------------------------------------------
__device__ __forceinline__ uint32_t to_tf32(float x) {
    uint32_t y;
    asm("cvt.rna.tf32.f32 %0, %1;" : "=r"(y) : "f"(x));
    return y;
}
__device__ __forceinline__ float to_tf32f(float x) {
    return __uint_as_float(to_tf32(x));
}

// ---------------- cp.async helpers ------------------------------------------
__device__ __forceinline__ void cp16(uint32_t dst, const float* src) {
    asm volatile("cp.async.cg.shared.global [%0], [%1], 16;\n"
                 :: "r"(dst), "l"(src));
}
__device__ __forceinline__ void cp4z(uint32_t dst, const float* src, int sz) {
    asm volatile("cp.async.ca.shared.global [%0], [%1], 4, %2;\n"
                 :: "r"(dst), "l"(src), "r"(sz));
}
__device__ __forceinline__ void cp_commit() {
    asm volatile("cp.async.commit_group;\n");
}
__device__ __forceinline__ void cp_wait1() {
    asm volatile("cp.async.wait_group 1;\n");
}

// ---------------- weight permute+convert: pw[m][r*256+ci] = w[m][ci*9+r] ----
__global__ void permw_kernel(const float* __restrict__ w, float* __restrict__ pw) {
    int idx = blockIdx.x * 256 + threadIdx.x;   // covers 256*2304
    int m = idx / KC;
    int k = idx - m*KC;
    int r = k >> 8;
    int ci = k & 255;
    pw[idx] = to_tf32f(w[m*KC + ci*9 + r]);
}

// ---------------- elementwise tf32 convert ----------------------------------
__global__ void cvt_kernel(const float* __restrict__ in, float* __restrict__ out) {
    long idx = (long)blockIdx.x * 256 + threadIdx.x;
    out[idx] = to_tf32f(in[idx]);
}

// ---------------- FiLM: film[b][co] = emb[b] @ noise_w + noise_b -----------
__global__ void film_kernel(const float* __restrict__ emb,
                            const float* __restrict__ w,
                            const float* __restrict__ nb,
                            float* __restrict__ film) {
    int b = blockIdx.x;
    int co = threadIdx.x;
    __shared__ float e[NC];
    e[co] = emb[b*NC + co];
    __syncthreads();
    float acc = nb[co];
    #pragma unroll 8
    for (int k = 0; k < NC; k++) acc += e[k] * w[k*NC + co];
    film[b*NC + co] = acc;
}

// ---------------- GroupNorm stats ------------------------------------------
__global__ void gn_stats_kernel(const float* __restrict__ x,
                                float* __restrict__ mean,
                                float* __restrict__ rstd) {
    int bg = blockIdx.x;                      // 0..511
    const float* p = x + (long)bg * 8192;
    int t = threadIdx.x;
    float s = 0.f, s2 = 0.f;
    for (int i = t; i < 8192; i += 256) {
        float v = p[i];
        s += v; s2 += v*v;
    }
    __shared__ float sh[256], sh2[256];
    sh[t] = s; sh2[t] = s2;
    __syncthreads();
    for (int o = 128; o > 0; o >>= 1) {
        if (t < o) { sh[t] += sh[t+o]; sh2[t] += sh2[t+o]; }
        __syncthreads();
    }
    if (t == 0) {
        float m = sh[0] * (1.f/8192.f);
        float var = sh2[0] * (1.f/8192.f) - m*m;
        mean[bg] = m;
        rstd[bg] = rsqrtf(var + 1e-5f);
    }
}

// ---------------- GroupNorm apply (+optional SiLU), tf32-rounded output -----
__global__ void gn_apply_kernel(const float* __restrict__ x,
                                const float* __restrict__ mean,
                                const float* __restrict__ rstd,
                                const float* __restrict__ scale,
                                const float* __restrict__ bias,
                                float* __restrict__ y,
                                int do_silu) {
    long idx = (long)blockIdx.x * 256 + threadIdx.x;
    int b   = (int)(idx >> 18);
    int ofs = (int)(idx & (CHW-1));
    int g   = ofs >> 13;
    int c   = ofs >> 10;
    int bg  = b*NG + g;
    float v = (x[idx] - mean[bg]) * rstd[bg] * scale[c] + bias[c];
    if (do_silu) v = v / (1.f + expf(-v));
    y[idx] = to_tf32f(v);
}

// ---------------- Softmax over rows of 1024, tf32-rounded output ------------
__global__ void softmax_kernel(float* __restrict__ S) {
    long row = blockIdx.x;
    float* p = S + row * NHW;
    int t = threadIdx.x;
    float v[4];
    float mx = -1e30f;
    #pragma unroll
    for (int j = 0; j < 4; j++) { v[j] = p[t + j*256]; mx = fmaxf(mx, v[j]); }
    __shared__ float sh[256];
    sh[t] = mx; __syncthreads();
    for (int o = 128; o > 0; o >>= 1) { if (t < o) sh[t] = fmaxf(sh[t], sh[t+o]); __syncthreads(); }
    mx = sh[0]; __syncthreads();
    float s = 0.f;
    #pragma unroll
    for (int j = 0; j < 4; j++) { v[j] = expf(v[j] - mx); s += v[j]; }
    sh[t] = s; __syncthreads();
    for (int o = 128; o > 0; o >>= 1) { if (t < o) sh[t] += sh[t+o]; __syncthreads(); }
    float inv = 1.f / sh[0];
    #pragma unroll
    for (int j = 0; j < 4; j++) p[t + j*256] = to_tf32f(v[j] * inv);
}

__device__ __forceinline__ void mma_tf32(float c[4], uint32_t a0, uint32_t a1,
                                         uint32_t a2, uint32_t a3,
                                         uint32_t b0, uint32_t b1) {
    asm volatile(
        "mma.sync.aligned.m16n8k8.row.col.f32.tf32.tf32.f32 "
        "{%0,%1,%2,%3}, {%4,%5,%6,%7}, {%8,%9}, {%0,%1,%2,%3};\n"
        : "+f"(c[0]), "+f"(c[1]), "+f"(c[2]), "+f"(c[3])
        : "r"(a0), "r"(a1), "r"(a2), "r"(a3), "r"(b0), "r"(b1));
}

// ---------------- Batched 256x128x16 TF32 GEMM, 3-stage cp.async ------------
// All inputs PRE-ROUNDED tf32 bits; 8 warps as 4m x 2n, 64x64 warp tiles.
// C[b][m][n] = alpha * sum_k A(m,k)*B(k,n) (+bias[m]) (+film[b][m])
//             (+addsrc[b][m][n]) (+= C if accumulate) (tf32-round if RND)
// TA=0: A row-major [M][K], smem [m][k] stride 20
// TA=1: A is [K][M],        smem [k][m] stride 264
// TB=0: B is [K][N],        smem [k][n] stride 136
// TB=1: B is [N][K],        smem [n][k] stride 20
// IMC : B image [Ci][32][32], K=9*Ci with k=r*256+ci (tap-major); [k][n] 136.
#define SA0 20
#define SAM 264
#define SKN 136
#define SNK 20
#define ASZ 5120            // max(256*20, 16*264)
#define BSZ 2560            // max(16*136, 128*20)
#define STG (ASZ+BSZ)       // floats per stage
#define GEMM_SMEM (3*STG*4) // 92160 bytes

template<int TA, int TB, bool IMC, int RND>
__global__ __launch_bounds__(256)
void gemm_tc_kernel(const float* __restrict__ A,
                    const float* __restrict__ Bp,
                    float* __restrict__ Cp,
                    int M, int N, int K,
                    long sA, long sB, long sC,
                    float alpha,
                    const float* __restrict__ bias,
                    const float* __restrict__ film,
                    const float* __restrict__ addsrc,
                    int accumulate) {
    extern __shared__ __align__(16) float smem[];

    int b  = blockIdx.z;
    const float* Ab = A  + (long)b * sA;
    const float* Bb = Bp + (long)b * sB;
    float*       Cb = Cp + (long)b * sC;
    int m0 = blockIdx.y * 256;
    int n0 = blockIdx.x * 128;
    int t    = threadIdx.x;
    int lane = t & 31;
    int wid  = t >> 5;
    int wm   = wid >> 1;         // warp m index (0..3) -> 64 rows
    int wn   = wid & 1;          // warp n index (0..1) -> 64 cols
    int grp  = lane >> 2;        // 0..7
    int qd   = lane & 3;         // 0..3

    uint32_t sb = (uint32_t)__cvta_generic_to_shared(&smem[0]);

    float acc[4][8][4];
    #pragma unroll
    for (int i = 0; i < 4; i++)
        #pragma unroll
        for (int j = 0; j < 8; j++)
            #pragma unroll
            for (int r = 0; r < 4; r++) acc[i][j][r] = 0.f;

    // im2col per-thread constants
    int ic_n  = t & 127;
    int ic_kr = t >> 7;                    // 0..1
    int ic_h  = (n0 + ic_n) >> 5;
    int ic_w  = (n0 + ic_n) & 31;

    auto prefA = [&](int kk, int s) {
        uint32_t ab = sb + (uint32_t)(s*STG)*4u;
        if (TA == 0) {
            #pragma unroll
            for (int r = 0; r < 4; r++) {       // 256x16 = 1024 float4
                int c = t + r*256;
                int m = c >> 2;
                int kq = (c & 3) << 2;
                cp16(ab + (uint32_t)(m*SA0 + kq)*4u,
                     Ab + (long)(m0+m)*K + kk + kq);
            }
        } else {
            #pragma unroll
            for (int r = 0; r < 4; r++) {       // 16x256 = 1024 float4
                int c = t + r*256;
                int k = c >> 6;
                int mq = (c & 63) << 2;
                cp16(ab + (uint32_t)(k*SAM + mq)*4u,
                     Ab + (long)(kk+k)*M + m0 + mq);
            }
        }
    };
    auto prefB = [&](int kk, int s) {
        uint32_t bbase = sb + (uint32_t)(s*STG + ASZ)*4u;
        if (IMC) {
            int r   = kk >> 8;            // constant tap for this tile
            int ci0 = (kk & 255) + ic_kr*8;
            int kh  = r / 3, kw = r - kh*3;
            int ih  = ic_h + kh - 1, iw = ic_w + kw - 1;
            bool ok = (ih >= 0 && ih < 32 && iw >= 0 && iw < 32);
            const float* src = ok ? (Bb + (long)ci0*NHW + ih*32 + iw) : Bb;
            int sz = ok ? 4 : 0;
            #pragma unroll
            for (int j = 0; j < 8; j++)
                cp4z(bbase + (uint32_t)((ic_kr*8 + j)*SKN + ic_n)*4u,
                     src + j*NHW, sz);
        } else if (TB == 0) {
            #pragma unroll
            for (int r = 0; r < 2; r++) {       // 16x128 = 512 float4
                int c = t + r*256;
                int k = c >> 5;
                int nq = (c & 31) << 2;
                cp16(bbase + (uint32_t)(k*SKN + nq)*4u,
                     Bb + (long)(kk+k)*N + n0 + nq);
            }
        } else {
            #pragma unroll
            for (int r = 0; r < 2; r++) {       // 128x16 = 512 float4
                int c = t + r*256;
                int n = c >> 2;
                int kq = (c & 3) << 2;
                cp16(bbase + (uint32_t)(n*SNK + kq)*4u,
                     Bb + (long)(n0+n)*K + kk + kq);
            }
        }
    };
    auto compute = [&](int s) {
        const uint32_t* AsU = reinterpret_cast<const uint32_t*>(&smem[s*STG]);
        const uint32_t* BsU = reinterpret_cast<const uint32_t*>(&smem[s*STG + ASZ]);
        #pragma unroll
        for (int ks = 0; ks < 16; ks += 8) {
            uint32_t af[4][4];
            #pragma unroll
            for (int mt = 0; mt < 4; mt++) {
                int mb = wm*64 + mt*16 + grp;
                if (TA == 0) {
                    af[mt][0] = AsU[mb*SA0 + ks + qd];
                    af[mt][1] = AsU[(mb+8)*SA0 + ks + qd];
                    af[mt][2] = AsU[mb*SA0 + ks + 4 + qd];
                    af[mt][3] = AsU[(mb+8)*SA0 + ks + 4 + qd];
                } else {
                    af[mt][0] = AsU[(ks+qd)*SAM + mb];
                    af[mt][1] = AsU[(ks+qd)*SAM + mb + 8];
                    af[mt][2] = AsU[(ks+4+qd)*SAM + mb];
                    af[mt][3] = AsU[(ks+4+qd)*SAM + mb + 8];
                }
            }
            uint32_t bf[8][2];
            #pragma unroll
            for (int nt = 0; nt < 8; nt++) {
                int nb = wn*64 + nt*8 + grp;
                if (TB == 1) {
                    bf[nt][0] = BsU[nb*SNK + ks + qd];
                    bf[nt][1] = BsU[nb*SNK + ks + 4 + qd];
                } else {
                    bf[nt][0] = BsU[(ks+qd)*SKN + nb];
                    bf[nt][1] = BsU[(ks+4+qd)*SKN + nb];
                }
            }
            #pragma unroll
            for (int mt = 0; mt < 4; mt++)
                #pragma unroll
                for (int nt = 0; nt < 8; nt++)
                    mma_tf32(acc[mt][nt], af[mt][0], af[mt][1], af[mt][2], af[mt][3],
                             bf[nt][0], bf[nt][1]);
        }
    };

    // ---- 3-stage pipelined mainloop ----
    int T = K >> 4;                        // k-tiles (K multiple of 16, >=16)
    prefA(0, 0); prefB(0, 0); cp_commit();
    prefA(16, 1); prefB(16, 1); cp_commit();
    for (int i = 0; i < T; i++) {
        cp_wait1();                        // tile i complete
        __syncthreads();
        if (i + 2 < T) {
            int s2 = (i + 2) % 3;
            prefA((i+2)*16, s2); prefB((i+2)*16, s2);
        }
        cp_commit();
        compute(i % 3);
        __syncthreads();
    }

    // ---- epilogue ----
    #pragma unroll
    for (int mt = 0; mt < 4; mt++) {
        int mr0 = m0 + wm*64 + mt*16 + grp;
        int mr1 = mr0 + 8;
        float badd0 = 0.f, badd1 = 0.f;
        if (bias) { badd0 += bias[mr0]; badd1 += bias[mr1]; }
        if (film) { badd0 += film[b*M + mr0]; badd1 += film[b*M + mr1]; }
        #pragma unroll
        for (int nt = 0; nt < 8; nt++) {
            int nc = n0 + wn*64 + nt*8 + qd*2;
            long i0 = (long)mr0 * N + nc;
            long i1 = (long)mr1 * N + nc;
            float v00 = acc[mt][nt][0] * alpha + badd0;
            float v01 = acc[mt][nt][1] * alpha + badd0;
            float v10 = acc[mt][nt][2] * alpha + badd1;
            float v11 = acc[mt][nt][3] * alpha + badd1;
            if (addsrc) {
                v00 += addsrc[(long)b*sC + i0];
                v01 += addsrc[(long)b*sC + i0 + 1];
                v10 += addsrc[(long)b*sC + i1];
                v11 += addsrc[(long)b*sC + i1 + 1];
            }
            if (accumulate) {
                v00 += Cb[i0]; v01 += Cb[i0 + 1];
                v10 += Cb[i1]; v11 += Cb[i1 + 1];
            }
            if (RND) {
                v00 = to_tf32f(v00); v01 = to_tf32f(v01);
                v10 = to_tf32f(v10); v11 = to_tf32f(v11);
            }
            *reinterpret_cast<float2*>(&Cb[i0]) = make_float2(v00, v01);
            *reinterpret_cast<float2*>(&Cb[i1]) = make_float2(v10, v11);
        }
    }
}

// ---------------- host launch ------------------------------------------------
extern "C" void kernel_launch(void* const* d_in, const int* in_sizes, int n_in,
                              void* d_out, int out_size) {
    const float* x          = (const float*)d_in[0];
    const float* noise_emb  = (const float*)d_in[1];
    const float* gn1_scale  = (const float*)d_in[2];
    const float* gn1_bias   = (const float*)d_in[3];
    const float* conv1_w    = (const float*)d_in[4];
    const float* conv1_b    = (const float*)d_in[5];
    const float* noise_w    = (const float*)d_in[6];
    const float* noise_b    = (const float*)d_in[7];
    const float* gn2_scale  = (const float*)d_in[8];
    const float* gn2_bias   = (const float*)d_in[9];
    const float* conv2_w    = (const float*)d_in[10];
    const float* conv2_b    = (const float*)d_in[11];
    const float* res_w      = (const float*)d_in[12];
    const float* res_b      = (const float*)d_in[13];
    const float* agn_scale  = (const float*)d_in[14];
    const float* agn_bias   = (const float*)d_in[15];
    const float* qkv_w      = (const float*)d_in[16];
    const float* out_w      = (const float*)d_in[17];
    const float* out_b      = (const float*)d_in[18];
    float* out = (float*)d_out;

    float *t0, *t1, *t2, *h, *qkv, *att, *film, *mean, *rstd;
    float *pw1, *pw2, *wq, *wr, *wo, *xc;
    cudaGetSymbolAddress((void**)&t0,   g_t0);
    cudaGetSymbolAddress((void**)&t1,   g_t1);
    cudaGetSymbolAddress((void**)&t2,   g_t2);
    cudaGetSymbolAddress((void**)&h,    g_h);
    cudaGetSymbolAddress((void**)&qkv,  g_qkv);
    cudaGetSymbolAddress((void**)&att,  g_att);
    cudaGetSymbolAddress((void**)&film, g_film);
    cudaGetSymbolAddress((void**)&mean, g_mean);
    cudaGetSymbolAddress((void**)&rstd, g_rstd);
    cudaGetSymbolAddress((void**)&pw1,  g_pw1);
    cudaGetSymbolAddress((void**)&pw2,  g_pw2);
    cudaGetSymbolAddress((void**)&wq,   g_wq);
    cudaGetSymbolAddress((void**)&wr,   g_wr);
    cudaGetSymbolAddress((void**)&wo,   g_wo);
    cudaGetSymbolAddress((void**)&xc,   g_xc);

    // allow 90KB dynamic smem on all GEMM instantiations
    cudaFuncSetAttribute(gemm_tc_kernel<0,0,true,0>,
        cudaFuncAttributeMaxDynamicSharedMemorySize, GEMM_SMEM);
    cudaFuncSetAttribute(gemm_tc_kernel<0,0,false,0>,
        cudaFuncAttributeMaxDynamicSharedMemorySize, GEMM_SMEM);
    cudaFuncSetAttribute(gemm_tc_kernel<0,0,false,1>,
        cudaFuncAttributeMaxDynamicSharedMemorySize, GEMM_SMEM);
    cudaFuncSetAttribute(gemm_tc_kernel<1,0,false,0>,
        cudaFuncAttributeMaxDynamicSharedMemorySize, GEMM_SMEM);
    cudaFuncSetAttribute(gemm_tc_kernel<0,1,false,1>,
        cudaFuncAttributeMaxDynamicSharedMemorySize, GEMM_SMEM);

    const int ELTS = NB * CHW;            // 4194304
    const int EW_GRID = ELTS / 256;       // 16384
    const int PW_GRID = NC*KC/256;        // 2304

    // one-shot weight/input conversions (tf32 bit patterns)
    permw_kernel<<<PW_GRID, 256>>>(conv1_w, pw1);
    permw_kernel<<<PW_GRID, 256>>>(conv2_w, pw2);
    cvt_kernel<<<3*NC*NC/256, 256>>>(qkv_w, wq);
    cvt_kernel<<<NC*NC/256, 256>>>(res_w, wr);
    cvt_kernel<<<NC*NC/256, 256>>>(out_w, wo);
    cvt_kernel<<<EW_GRID, 256>>>(x, xc);

    // FiLM vector
    film_kernel<<<NB, NC>>>(noise_emb, noise_w, noise_b, film);

    // GN1 + SiLU (tf32 out)
    gn_stats_kernel<<<NB*NG, 256>>>(x, mean, rstd);
    gn_apply_kernel<<<EW_GRID, 256>>>(x, mean, rstd, gn1_scale, gn1_bias, t0, 1);

    // conv1 (3x3, tap-major im2col GEMM) + FiLM add fused
    gemm_tc_kernel<0,0,true,0><<<dim3(8,1,NB), 256, GEMM_SMEM>>>(
        pw1, t0, t1, NC, NHW, KC, 0, CHW, CHW, 1.f,
        conv1_b, film, nullptr, 0);

    // GN2 + SiLU (tf32 out)
    gn_stats_kernel<<<NB*NG, 256>>>(t1, mean, rstd);
    gn_apply_kernel<<<EW_GRID, 256>>>(t1, mean, rstd, gn2_scale, gn2_bias, t2, 1);

    // residual 1x1 conv -> h (fp32 out)
    gemm_tc_kernel<0,0,false,0><<<dim3(8,1,NB), 256, GEMM_SMEM>>>(
        wr, xc, h, NC, NHW, NC, 0, CHW, CHW, 1.f,
        res_b, nullptr, nullptr, 0);

    // conv2 (3x3) accumulates into h (fp32)
    gemm_tc_kernel<0,0,true,0><<<dim3(8,1,NB), 256, GEMM_SMEM>>>(
        pw2, t2, h, NC, NHW, KC, 0, CHW, CHW, 1.f,
        conv2_b, nullptr, nullptr, 1);

    // attention GroupNorm (no SiLU, tf32 out) -> t0
    gn_stats_kernel<<<NB*NG, 256>>>(h, mean, rstd);
    gn_apply_kernel<<<EW_GRID, 256>>>(h, mean, rstd, agn_scale, agn_bias, t0, 0);

    // qkv 1x1 conv (no bias), output tf32-rounded
    gemm_tc_kernel<0,0,false,1><<<dim3(8,3,NB), 256, GEMM_SMEM>>>(
        wq, t0, qkv, 3*NC, NHW, NC, 0, CHW, (long)3*CHW, 1.f,
        nullptr, nullptr, nullptr, 0);

    // scores: S[b][s][t] = (1/16) * sum_d q[d][s] k[d][t]   (A is [K][M])
    gemm_tc_kernel<1,0,false,0><<<dim3(8,4,NB), 256, GEMM_SMEM>>>(
        qkv /*q*/, qkv + CHW /*k*/, att, NHW, NHW, NC,
        (long)3*CHW, (long)3*CHW, (long)NHW*NHW, 0.0625f,
        nullptr, nullptr, nullptr, 0);

    // softmax rows (tf32 out)
    softmax_kernel<<<NB*NHW, 256>>>(att);

    // AV: O[b][d][s] = sum_t v[d][t] S[s][t] (B is [N][K]), tf32-rounded out
    gemm_tc_kernel<0,1,false,1><<<dim3(8,1,NB), 256, GEMM_SMEM>>>(
        qkv + 2*CHW /*v*/, att, t2, NC, NHW, NHW,
        (long)3*CHW, (long)NHW*NHW, CHW, 1.f,
        nullptr, nullptr, nullptr, 0);

    // out 1x1 conv + bias + residual h -> d_out (fp32)
    gemm_tc_kernel<0,0,false,0><<<dim3(8,1,NB), 256, GEMM_SMEM>>>(
        wo, t2, out, NC, NHW, NC, 0, CHW, CHW, 1.f,
        out_b, nullptr, h, 0);
}